// round 8
// baseline (speedup 1.0000x reference)
#include <cuda_runtime.h>
#include <cuda_fp16.h>
#include <cstdint>

// ============================================================================
// Attention: softmax(Q K^T) V, B=4 H=16 S=2048 D=64, fp32 in/out.
// FA2-style mma.sync kernel, split-fp16 QK^T (rel_err ~2e-4), cp.async
// double-buffered K/V staging.
// R7 change: TM 128->64, 128 threads/CTA, 2 CTAs/SM (independent barriers
// per SMSP) so one CTA's MMAs overlap the other's softmax/convert/sync.
// ============================================================================

#define DINLINE __device__ __forceinline__

static constexpr int S_LEN = 2048;
static constexpr int HDIM  = 64;
static constexpr int TM    = 64;           // Q rows per CTA
static constexpr int TN    = 64;           // K/V rows per iteration
static constexpr int NIT   = S_LEN / TN;   // 32
static constexpr int NTHREADS = 128;       // 4 warps
static constexpr int NQT   = S_LEN / TM;   // 32 Q tiles per head

// dynamic SMEM layout (bytes)
static constexpr int SM_QH = 0;            // 64 x 64 fp16 SW128 ( 8 KB)
static constexpr int SM_QL = 8192;         // 64 x 64 fp16 SW128 ( 8 KB)
static constexpr int SM_KH = 16384;        // 64 x 64 fp16 SW128 ( 8 KB)
static constexpr int SM_KL = 24576;        // 64 x 64 fp16 SW128 ( 8 KB)
static constexpr int SM_V  = 32768;        // 64 x 64 fp16 SW128 ( 8 KB)
static constexpr int SM_ST = 40960;        // fp32 staging: 2 x (K 16K + V 16K)
static constexpr int ST_STRIDE = 32768;
static constexpr int ST_V_OFF  = 16384;
static constexpr int SMEM_BYTES = SM_ST + 2 * ST_STRIDE;   // 104 KB

// ---------------------------------------------------------------------------
DINLINE uint32_t smem_u32(const void* p) {
    uint32_t a;
    asm("{ .reg .u64 t; cvta.to.shared.u64 t, %1; cvt.u32.u64 %0, t; }" : "=r"(a) : "l"(p));
    return a;
}

DINLINE float ex2f(float x) {
    float y;
    asm("ex2.approx.ftz.f32 %0, %1;" : "=f"(y) : "f"(x));
    return y;
}

DINLINE uint32_t h2_bits(__half2 h) {
    uint32_t u;
    __builtin_memcpy(&u, &h, 4);
    return u;
}

// swizzled SMEM address: tile base + SW128(row*128 + colbyte)
DINLINE uint32_t sw_addr(uint32_t base, int row, int colb) {
    uint32_t off = (uint32_t)(row * 128 + colb);
    return base + (off ^ ((off >> 3) & 0x70));
}

DINLINE void ldmatrix_x4(uint32_t* r, uint32_t addr) {
    asm volatile("ldmatrix.sync.aligned.m8n8.x4.shared.b16 {%0,%1,%2,%3}, [%4];"
                 : "=r"(r[0]), "=r"(r[1]), "=r"(r[2]), "=r"(r[3]) : "r"(addr));
}

DINLINE void ldmatrix_x4_trans(uint32_t* r, uint32_t addr) {
    asm volatile("ldmatrix.sync.aligned.m8n8.x4.trans.shared.b16 {%0,%1,%2,%3}, [%4];"
                 : "=r"(r[0]), "=r"(r[1]), "=r"(r[2]), "=r"(r[3]) : "r"(addr));
}

DINLINE void mma_16816(float* c, const uint32_t* a, uint32_t b0, uint32_t b1) {
    asm volatile(
        "mma.sync.aligned.m16n8k16.row.col.f32.f16.f16.f32 "
        "{%0,%1,%2,%3}, {%4,%5,%6,%7}, {%8,%9}, {%0,%1,%2,%3};"
        : "+f"(c[0]), "+f"(c[1]), "+f"(c[2]), "+f"(c[3])
        : "r"(a[0]), "r"(a[1]), "r"(a[2]), "r"(a[3]), "r"(b0), "r"(b1));
}

DINLINE void sts_v2(uint32_t addr, uint32_t x, uint32_t y) {
    asm volatile("st.shared.v2.b32 [%0], {%1, %2};" :: "r"(addr), "r"(x), "r"(y) : "memory");
}

DINLINE float4 lds_v4f(uint32_t addr) {
    float4 v;
    asm volatile("ld.shared.v4.f32 {%0,%1,%2,%3}, [%4];"
                 : "=f"(v.x), "=f"(v.y), "=f"(v.z), "=f"(v.w) : "r"(addr));
    return v;
}

// Split-precision pack: hi = fp16(x), lo = fp16(x - hi)
DINLINE void split2(float x, float y, uint32_t& hi, uint32_t& lo) {
    __half hx = __float2half_rn(x);
    __half hy = __float2half_rn(y);
    __half lx = __float2half_rn(x - __half2float(hx));
    __half ly = __float2half_rn(y - __half2float(hy));
    hi = h2_bits(__halves2half2(hx, hy));
    lo = h2_bits(__halves2half2(lx, ly));
}

// cp.async a 64x64 fp32 tile (16 KB) gmem -> SMEM staging. 8 x 16B per thread.
DINLINE void cp_async_tile(const float* __restrict__ g, uint32_t s) {
    const int t = threadIdx.x;
#pragma unroll
    for (int i = 0; i < 8; i++) {
        int idx = t + i * NTHREADS;               // 16B chunk index
        asm volatile("cp.async.cg.shared.global [%0], [%1], 16;"
                     :: "r"(s + idx * 16), "l"(g + idx * 4) : "memory");
    }
}
#define CP_COMMIT() asm volatile("cp.async.commit_group;" ::: "memory")
#define CP_WAIT0()  asm volatile("cp.async.wait_group 0;" ::: "memory")

// Convert fp32 staging (SMEM) -> split hi/lo fp16 SW128 tiles. 64 rows.
DINLINE void convert_split_64(uint32_t sf32, uint32_t shi, uint32_t slo) {
    const int t = threadIdx.x;
#pragma unroll
    for (int i = 0; i < 8; i++) {
        int idx = t + i * NTHREADS;
        int row = idx >> 4, c4 = idx & 15;
        float4 v = lds_v4f(sf32 + idx * 16);      // own cp.async chunk
        uint32_t h0, l0, h1, l1;
        split2(v.x, v.y, h0, l0);
        split2(v.z, v.w, h1, l1);
        sts_v2(sw_addr(shi, row, c4 * 8), h0, h1);
        sts_v2(sw_addr(slo, row, c4 * 8), l0, l1);
    }
}

// Convert fp32 staging -> plain fp16 SW128 tile (V). 64 rows.
DINLINE void convert_plain_64(uint32_t sf32, uint32_t sbase) {
    const int t = threadIdx.x;
#pragma unroll
    for (int i = 0; i < 8; i++) {
        int idx = t + i * NTHREADS;
        int row = idx >> 4, c4 = idx & 15;
        float4 v = lds_v4f(sf32 + idx * 16);
        __half2 a = __floats2half2_rn(v.x, v.y);
        __half2 b = __floats2half2_rn(v.z, v.w);
        sts_v2(sw_addr(sbase, row, c4 * 8), h2_bits(a), h2_bits(b));
    }
}

// Q: direct gmem load -> split fp16 tiles (64 rows, runs once)
DINLINE void load_q_split(const float* __restrict__ g, uint32_t shi, uint32_t slo) {
    const int t = threadIdx.x;
    const float scale = 1.4426950408889634f;   // log2(e)
#pragma unroll
    for (int i = 0; i < 8; i++) {
        int idx = t + i * NTHREADS;
        int row = idx >> 4, c4 = idx & 15;
        float4 v = *reinterpret_cast<const float4*>(g + row * HDIM + c4 * 4);
        uint32_t h0, l0, h1, l1;
        split2(v.x * scale, v.y * scale, h0, l0);
        split2(v.z * scale, v.w * scale, h1, l1);
        sts_v2(sw_addr(shi, row, c4 * 8), h0, h1);
        sts_v2(sw_addr(slo, row, c4 * 8), l0, l1);
    }
}

// ---------------------------------------------------------------------------
__global__ void __launch_bounds__(NTHREADS, 2)
attn_kernel(const float* __restrict__ Q, const float* __restrict__ K,
            const float* __restrict__ V, float* __restrict__ Out) {
    extern __shared__ char smem[];
    const uint32_t sb = smem_u32(smem);

    const int tid = threadIdx.x;
    const int w   = tid >> 5;        // 0..3
    const int lid = tid & 31;
    const int g   = lid >> 2;
    const int tig = lid & 3;

    const int bh = blockIdx.x >> 5;          // 64 heads
    const int qt = blockIdx.x & 31;          // 32 Q tiles of 64 rows
    const size_t head_off = (size_t)bh * S_LEN * HDIM;
    const float* qg = Q + head_off + (size_t)qt * TM * HDIM;
    const float* kg = K + head_off;
    const float* vg = V + head_off;
    float* og = Out + head_off + (size_t)qt * TM * HDIM;

    // ---- prologue: prefetch K0/V0, stage Q, build Q frags ----
    cp_async_tile(kg, sb + SM_ST);
    cp_async_tile(vg, sb + SM_ST + ST_V_OFF);
    CP_COMMIT();

    load_q_split(qg, sb + SM_QH, sb + SM_QL);
    __syncthreads();

    uint32_t qh[4][4], ql[4][4];
    {
        const int r   = lid & 7;
        const int sel = lid >> 3;
        const int row = 16 * w + (sel & 1) * 8 + r;
#pragma unroll
        for (int kb = 0; kb < 4; kb++) {
            int colb = kb * 32 + (sel >> 1) * 16;
            ldmatrix_x4(qh[kb], sw_addr(sb + SM_QH, row, colb));
            ldmatrix_x4(ql[kb], sw_addr(sb + SM_QL, row, colb));
        }
    }

    float oacc[8][4];
#pragma unroll
    for (int nb = 0; nb < 8; nb++)
#pragma unroll
        for (int i = 0; i < 4; i++) oacc[nb][i] = 0.f;

    float m0 = -__int_as_float(0x7f800000), m1 = m0;
    float l0 = 0.f, l1 = 0.f;

    const int lr   = lid & 7;
    const int lsel = lid >> 3;

    for (int j = 0; j < NIT; j++) {
        const uint32_t st = sb + SM_ST + (j & 1) * ST_STRIDE;

        // ---- wait own cp.async chunks, convert staging -> fp16 tiles ----
        CP_WAIT0();
        convert_split_64(st, sb + SM_KH, sb + SM_KL);
        convert_plain_64(st + ST_V_OFF, sb + SM_V);

        // ---- prefetch tile j+1 (overlaps with MMA/softmax below) ----
        if (j + 1 < NIT) {
            const uint32_t stn = sb + SM_ST + ((j + 1) & 1) * ST_STRIDE;
            cp_async_tile(kg + (size_t)(j + 1) * TN * HDIM, stn);
            cp_async_tile(vg + (size_t)(j + 1) * TN * HDIM, stn + ST_V_OFF);
            CP_COMMIT();
        }
        __syncthreads();   // fp16 tiles visible to all warps

        // ---- S = Qhi Khi^T + Qlo Khi^T + Qhi Klo^T : 16 x 64 per warp ----
        float sacc[8][4];
#pragma unroll
        for (int nb = 0; nb < 8; nb++) {
#pragma unroll
            for (int i = 0; i < 4; i++) sacc[nb][i] = 0.f;
#pragma unroll
            for (int kbp = 0; kbp < 2; kbp++) {
                uint32_t kh[4], kl[4];
                int colb = 64 * kbp + lsel * 16;
                ldmatrix_x4(kh, sw_addr(sb + SM_KH, 8 * nb + lr, colb));
                ldmatrix_x4(kl, sw_addr(sb + SM_KL, 8 * nb + lr, colb));
                mma_16816(sacc[nb], qh[2 * kbp],     kh[0], kh[1]);
                mma_16816(sacc[nb], qh[2 * kbp + 1], kh[2], kh[3]);
                mma_16816(sacc[nb], ql[2 * kbp],     kh[0], kh[1]);
                mma_16816(sacc[nb], ql[2 * kbp + 1], kh[2], kh[3]);
                mma_16816(sacc[nb], qh[2 * kbp],     kl[0], kl[1]);
                mma_16816(sacc[nb], qh[2 * kbp + 1], kl[2], kl[3]);
            }
        }

        // ---- online softmax ----
        float mr0 = sacc[0][0], mr1 = sacc[0][2];
#pragma unroll
        for (int nb = 0; nb < 8; nb++) {
            mr0 = fmaxf(mr0, fmaxf(sacc[nb][0], sacc[nb][1]));
            mr1 = fmaxf(mr1, fmaxf(sacc[nb][2], sacc[nb][3]));
        }
        mr0 = fmaxf(mr0, __shfl_xor_sync(0xffffffffu, mr0, 1));
        mr0 = fmaxf(mr0, __shfl_xor_sync(0xffffffffu, mr0, 2));
        mr1 = fmaxf(mr1, __shfl_xor_sync(0xffffffffu, mr1, 1));
        mr1 = fmaxf(mr1, __shfl_xor_sync(0xffffffffu, mr1, 2));

        float mn0 = fmaxf(m0, mr0), mn1 = fmaxf(m1, mr1);
        float al0 = ex2f(m0 - mn0), al1 = ex2f(m1 - mn1);
        m0 = mn0; m1 = mn1;

        float sum0 = 0.f, sum1 = 0.f;
#pragma unroll
        for (int nb = 0; nb < 8; nb++) {
            sacc[nb][0] = ex2f(sacc[nb][0] - mn0);
            sacc[nb][1] = ex2f(sacc[nb][1] - mn0);
            sacc[nb][2] = ex2f(sacc[nb][2] - mn1);
            sacc[nb][3] = ex2f(sacc[nb][3] - mn1);
            sum0 += sacc[nb][0] + sacc[nb][1];
            sum1 += sacc[nb][2] + sacc[nb][3];
        }
        sum0 += __shfl_xor_sync(0xffffffffu, sum0, 1);
        sum0 += __shfl_xor_sync(0xffffffffu, sum0, 2);
        sum1 += __shfl_xor_sync(0xffffffffu, sum1, 1);
        sum1 += __shfl_xor_sync(0xffffffffu, sum1, 2);
        l0 = l0 * al0 + sum0;
        l1 = l1 * al1 + sum1;

#pragma unroll
        for (int nb = 0; nb < 8; nb++) {
            oacc[nb][0] *= al0; oacc[nb][1] *= al0;
            oacc[nb][2] *= al1; oacc[nb][3] *= al1;
        }

        // pack P into A-fragments
        uint32_t pa[4][4];
#pragma unroll
        for (int kb2 = 0; kb2 < 4; kb2++) {
            pa[kb2][0] = h2_bits(__floats2half2_rn(sacc[2 * kb2][0],     sacc[2 * kb2][1]));
            pa[kb2][1] = h2_bits(__floats2half2_rn(sacc[2 * kb2][2],     sacc[2 * kb2][3]));
            pa[kb2][2] = h2_bits(__floats2half2_rn(sacc[2 * kb2 + 1][0], sacc[2 * kb2 + 1][1]));
            pa[kb2][3] = h2_bits(__floats2half2_rn(sacc[2 * kb2 + 1][2], sacc[2 * kb2 + 1][3]));
        }

        // ---- O += P V ----
#pragma unroll
        for (int nbp = 0; nbp < 4; nbp++) {
#pragma unroll
            for (int kb2 = 0; kb2 < 4; kb2++) {
                uint32_t vf[4];
                int row  = 16 * kb2 + (lsel & 1) * 8 + lr;
                int colb = 16 * (2 * nbp + (lsel >> 1));
                ldmatrix_x4_trans(vf, sw_addr(sb + SM_V, row, colb));
                mma_16816(oacc[2 * nbp],     pa[kb2], vf[0], vf[1]);
                mma_16816(oacc[2 * nbp + 1], pa[kb2], vf[2], vf[3]);
            }
        }
        __syncthreads();   // fp16 tiles consumed; next iter may overwrite
    }

    // ---- epilogue: O / l -> gmem ----
    float inv0 = __fdividef(1.f, l0);
    float inv1 = __fdividef(1.f, l1);
    const int row0 = 16 * w + g;
    const int row1 = row0 + 8;
#pragma unroll
    for (int nb = 0; nb < 8; nb++) {
        int col = 8 * nb + 2 * tig;
        *reinterpret_cast<float2*>(og + (size_t)row0 * HDIM + col) =
            make_float2(oacc[nb][0] * inv0, oacc[nb][1] * inv0);
        *reinterpret_cast<float2*>(og + (size_t)row1 * HDIM + col) =
            make_float2(oacc[nb][2] * inv1, oacc[nb][3] * inv1);
    }
}

// ---------------------------------------------------------------------------
extern "C" void kernel_launch(void* const* d_in, const int* in_sizes, int n_in,
                              void* d_out, int out_size) {
    const float* Q = (const float*)d_in[0];
    const float* K = (const float*)d_in[1];
    const float* V = (const float*)d_in[2];
    float* O = (float*)d_out;

    cudaFuncSetAttribute(attn_kernel, cudaFuncAttributeMaxDynamicSharedMemorySize, SMEM_BYTES);

    dim3 grid(64 * NQT);   // 2048 CTAs; 2 resident per SM
    dim3 block(NTHREADS);
    attn_kernel<<<grid, block, SMEM_BYTES>>>(Q, K, V, O);
}

// round 9
// speedup vs baseline: 1.2527x; 1.2527x over previous
#include <cuda_runtime.h>
#include <cuda_fp16.h>
#include <cstdint>

// ============================================================================
// Attention: softmax(Q K^T) V, B=4 H=16 S=2048 D=64, fp32 in/out.
// FA2-style mma.sync kernel, split-fp16 QK^T (rel_err ~2e-4).
// R8: pre-convert kernel writes K/V once per head as PRE-SWIZZLED split-fp16
// tiles (Khi/Klo/V) into __device__ scratch; the attention kernel cp.asyncs
// those tiles directly (double-buffered) — no in-loop conversion, no staging
// round-trip, 16x less convert work chip-wide. Numerics identical to R6.
// ============================================================================

#define DINLINE __device__ __forceinline__

static constexpr int S_LEN = 2048;
static constexpr int HDIM  = 64;
static constexpr int TM    = 128;          // Q rows per CTA
static constexpr int TN    = 64;           // K/V rows per iteration
static constexpr int NIT   = S_LEN / TN;   // 32
static constexpr int NTHREADS = 256;       // 8 warps
static constexpr int NHEADS = 64;
static constexpr int TILE_BYTES = TN * 128;          // 8192 (64 rows x 128B)
static constexpr int NTILES = NHEADS * NIT;          // 2048

// scratch: pre-swizzled fp16 tiles (Khi, Klo, V), 16 MB each
__device__ __align__(16) uint8_t d_khi[(size_t)NTILES * TILE_BYTES];
__device__ __align__(16) uint8_t d_klo[(size_t)NTILES * TILE_BYTES];
__device__ __align__(16) uint8_t d_vh [(size_t)NTILES * TILE_BYTES];

// main-kernel dynamic SMEM layout (bytes)
static constexpr int SM_QH = 0;            // 128 x 64 fp16 SW128 (16 KB)
static constexpr int SM_QL = 16384;        // 128 x 64 fp16 SW128 (16 KB)
static constexpr int SM_ST = 32768;        // 2 stages x (Khi 8K | Klo 8K | V 8K)
static constexpr int STAGE = 24576;
static constexpr int ST_KL = 8192;
static constexpr int ST_V  = 16384;
static constexpr int SMEM_BYTES = SM_ST + 2 * STAGE;   // 80 KB

// ---------------------------------------------------------------------------
DINLINE uint32_t smem_u32(const void* p) {
    uint32_t a;
    asm("{ .reg .u64 t; cvta.to.shared.u64 t, %1; cvt.u32.u64 %0, t; }" : "=r"(a) : "l"(p));
    return a;
}

DINLINE float ex2f(float x) {
    float y;
    asm("ex2.approx.ftz.f32 %0, %1;" : "=f"(y) : "f"(x));
    return y;
}

DINLINE uint32_t h2_bits(__half2 h) {
    uint32_t u;
    __builtin_memcpy(&u, &h, 4);
    return u;
}

DINLINE uint32_t sw_off(int row, int colb) {
    uint32_t off = (uint32_t)(row * 128 + colb);
    return off ^ ((off >> 3) & 0x70);
}

DINLINE uint32_t sw_addr(uint32_t base, int row, int colb) {
    return base + sw_off(row, colb);
}

DINLINE void ldmatrix_x4(uint32_t* r, uint32_t addr) {
    asm volatile("ldmatrix.sync.aligned.m8n8.x4.shared.b16 {%0,%1,%2,%3}, [%4];"
                 : "=r"(r[0]), "=r"(r[1]), "=r"(r[2]), "=r"(r[3]) : "r"(addr));
}

DINLINE void ldmatrix_x4_trans(uint32_t* r, uint32_t addr) {
    asm volatile("ldmatrix.sync.aligned.m8n8.x4.trans.shared.b16 {%0,%1,%2,%3}, [%4];"
                 : "=r"(r[0]), "=r"(r[1]), "=r"(r[2]), "=r"(r[3]) : "r"(addr));
}

DINLINE void mma_16816(float* c, const uint32_t* a, uint32_t b0, uint32_t b1) {
    asm volatile(
        "mma.sync.aligned.m16n8k16.row.col.f32.f16.f16.f32 "
        "{%0,%1,%2,%3}, {%4,%5,%6,%7}, {%8,%9}, {%0,%1,%2,%3};"
        : "+f"(c[0]), "+f"(c[1]), "+f"(c[2]), "+f"(c[3])
        : "r"(a[0]), "r"(a[1]), "r"(a[2]), "r"(a[3]), "r"(b0), "r"(b1));
}

DINLINE void sts_v2(uint32_t addr, uint32_t x, uint32_t y) {
    asm volatile("st.shared.v2.b32 [%0], {%1, %2};" :: "r"(addr), "r"(x), "r"(y) : "memory");
}

// Split-precision pack: hi = fp16(x), lo = fp16(x - hi)
DINLINE void split2(float x, float y, uint32_t& hi, uint32_t& lo) {
    __half hx = __float2half_rn(x);
    __half hy = __float2half_rn(y);
    __half lx = __float2half_rn(x - __half2float(hx));
    __half ly = __float2half_rn(y - __half2float(hy));
    hi = h2_bits(__halves2half2(hx, hy));
    lo = h2_bits(__halves2half2(lx, ly));
}

#define CP_COMMIT() asm volatile("cp.async.commit_group;" ::: "memory")
#define CP_WAIT0()  asm volatile("cp.async.wait_group 0;" ::: "memory")

// cp.async one pre-swizzled 8 KB tile (global scratch -> smem). 2 x 16B/thread.
DINLINE void cp_tile(const uint8_t* __restrict__ g, uint32_t s) {
    const int t = threadIdx.x;
#pragma unroll
    for (int i = 0; i < 2; i++) {
        int idx = t + i * NTHREADS;
        asm volatile("cp.async.cg.shared.global [%0], [%1], 16;"
                     :: "r"(s + idx * 16), "l"(g + idx * 16) : "memory");
    }
}

// ---------------------------------------------------------------------------
// Pre-pass: K/V fp32 -> pre-swizzled split-fp16 tiles in scratch.
// One block per 64-row tile (tiles are contiguous: tile*4096 floats).
// ---------------------------------------------------------------------------
__global__ void __launch_bounds__(256)
convert_kernel(const float* __restrict__ K, const float* __restrict__ V) {
    const int tile = blockIdx.x;
    const float* kg = K + (size_t)tile * (TN * HDIM);
    const float* vg = V + (size_t)tile * (TN * HDIM);
    uint8_t* okh = d_khi + (size_t)tile * TILE_BYTES;
    uint8_t* okl = d_klo + (size_t)tile * TILE_BYTES;
    uint8_t* ov  = d_vh  + (size_t)tile * TILE_BYTES;
    const int t = threadIdx.x;
#pragma unroll
    for (int i = 0; i < 4; i++) {
        int idx = t + i * 256;                 // float4 index, 0..1023
        int row = idx >> 4, c4 = idx & 15;
        uint32_t off = sw_off(row, c4 * 8);
        float4 kv = *reinterpret_cast<const float4*>(kg + idx * 4);
        uint32_t h0, l0, h1, l1;
        split2(kv.x, kv.y, h0, l0);
        split2(kv.z, kv.w, h1, l1);
        *reinterpret_cast<uint2*>(okh + off) = make_uint2(h0, h1);
        *reinterpret_cast<uint2*>(okl + off) = make_uint2(l0, l1);
        float4 vv = *reinterpret_cast<const float4*>(vg + idx * 4);
        *reinterpret_cast<uint2*>(ov + off) =
            make_uint2(h2_bits(__floats2half2_rn(vv.x, vv.y)),
                       h2_bits(__floats2half2_rn(vv.z, vv.w)));
    }
}

// Q: direct gmem load -> split fp16 tiles (once per CTA, 128 rows)
DINLINE void load_q_split(const float* __restrict__ g, uint32_t shi, uint32_t slo) {
    const int t = threadIdx.x;
    const float scale = 1.4426950408889634f;   // log2(e)
#pragma unroll
    for (int i = 0; i < 8; i++) {
        int idx = t + i * NTHREADS;
        int row = idx >> 4, c4 = idx & 15;
        float4 v = *reinterpret_cast<const float4*>(g + row * HDIM + c4 * 4);
        uint32_t h0, l0, h1, l1;
        split2(v.x * scale, v.y * scale, h0, l0);
        split2(v.z * scale, v.w * scale, h1, l1);
        sts_v2(sw_addr(shi, row, c4 * 8), h0, h1);
        sts_v2(sw_addr(slo, row, c4 * 8), l0, l1);
    }
}

// ---------------------------------------------------------------------------
__global__ void __launch_bounds__(NTHREADS, 1)
attn_kernel(const float* __restrict__ Q, float* __restrict__ Out) {
    extern __shared__ char smem[];
    const uint32_t sb = smem_u32(smem);

    const int tid = threadIdx.x;
    const int w   = tid >> 5;
    const int lid = tid & 31;
    const int g   = lid >> 2;
    const int tig = lid & 3;

    const int bh = blockIdx.x >> 4;          // head
    const int qt = blockIdx.x & 15;          // Q tile of 128 rows
    const size_t head_off = (size_t)bh * S_LEN * HDIM;
    const float* qg = Q + head_off + (size_t)qt * TM * HDIM;
    float* og = Out + head_off + (size_t)qt * TM * HDIM;
    const size_t tbase = (size_t)bh * NIT;   // first K/V tile of this head

    // ---- prologue: prefetch tile 0, stage Q, build Q frags ----
    cp_tile(d_khi + tbase * TILE_BYTES, sb + SM_ST);
    cp_tile(d_klo + tbase * TILE_BYTES, sb + SM_ST + ST_KL);
    cp_tile(d_vh  + tbase * TILE_BYTES, sb + SM_ST + ST_V);
    CP_COMMIT();

    load_q_split(qg, sb + SM_QH, sb + SM_QL);
    __syncthreads();

    uint32_t qh[4][4], ql[4][4];
    {
        const int r   = lid & 7;
        const int sel = lid >> 3;
        const int row = 16 * w + (sel & 1) * 8 + r;
#pragma unroll
        for (int kb = 0; kb < 4; kb++) {
            int colb = kb * 32 + (sel >> 1) * 16;
            ldmatrix_x4(qh[kb], sw_addr(sb + SM_QH, row, colb));
            ldmatrix_x4(ql[kb], sw_addr(sb + SM_QL, row, colb));
        }
    }

    float oacc[8][4];
#pragma unroll
    for (int nb = 0; nb < 8; nb++)
#pragma unroll
        for (int i = 0; i < 4; i++) oacc[nb][i] = 0.f;

    float m0 = -__int_as_float(0x7f800000), m1 = m0;
    float l0 = 0.f, l1 = 0.f;

    const int lr   = lid & 7;
    const int lsel = lid >> 3;

    for (int j = 0; j < NIT; j++) {
        const uint32_t st = sb + SM_ST + (j & 1) * STAGE;

        // tile j arrived; all warps done reading the other stage (iter j-1)
        CP_WAIT0();
        __syncthreads();

        // prefetch tile j+1 into the other stage (overlaps all MMAs below)
        if (j + 1 < NIT) {
            const uint32_t stn = sb + SM_ST + ((j + 1) & 1) * STAGE;
            const size_t toff = (tbase + j + 1) * TILE_BYTES;
            cp_tile(d_khi + toff, stn);
            cp_tile(d_klo + toff, stn + ST_KL);
            cp_tile(d_vh  + toff, stn + ST_V);
            CP_COMMIT();
        }

        // ---- S = Qhi Khi^T + Qlo Khi^T + Qhi Klo^T : 16 x 64 per warp ----
        float sacc[8][4];
#pragma unroll
        for (int nb = 0; nb < 8; nb++) {
#pragma unroll
            for (int i = 0; i < 4; i++) sacc[nb][i] = 0.f;
#pragma unroll
            for (int kbp = 0; kbp < 2; kbp++) {
                uint32_t kh[4], kl[4];
                int colb = 64 * kbp + lsel * 16;
                ldmatrix_x4(kh, sw_addr(st, 8 * nb + lr, colb));
                ldmatrix_x4(kl, sw_addr(st + ST_KL, 8 * nb + lr, colb));
                mma_16816(sacc[nb], qh[2 * kbp],     kh[0], kh[1]);
                mma_16816(sacc[nb], qh[2 * kbp + 1], kh[2], kh[3]);
                mma_16816(sacc[nb], ql[2 * kbp],     kh[0], kh[1]);
                mma_16816(sacc[nb], ql[2 * kbp + 1], kh[2], kh[3]);
                mma_16816(sacc[nb], qh[2 * kbp],     kl[0], kl[1]);
                mma_16816(sacc[nb], qh[2 * kbp + 1], kl[2], kl[3]);
            }
        }

        // ---- online softmax ----
        float mr0 = sacc[0][0], mr1 = sacc[0][2];
#pragma unroll
        for (int nb = 0; nb < 8; nb++) {
            mr0 = fmaxf(mr0, fmaxf(sacc[nb][0], sacc[nb][1]));
            mr1 = fmaxf(mr1, fmaxf(sacc[nb][2], sacc[nb][3]));
        }
        mr0 = fmaxf(mr0, __shfl_xor_sync(0xffffffffu, mr0, 1));
        mr0 = fmaxf(mr0, __shfl_xor_sync(0xffffffffu, mr0, 2));
        mr1 = fmaxf(mr1, __shfl_xor_sync(0xffffffffu, mr1, 1));
        mr1 = fmaxf(mr1, __shfl_xor_sync(0xffffffffu, mr1, 2));

        float mn0 = fmaxf(m0, mr0), mn1 = fmaxf(m1, mr1);
        float al0 = ex2f(m0 - mn0), al1 = ex2f(m1 - mn1);
        m0 = mn0; m1 = mn1;

        float sum0 = 0.f, sum1 = 0.f;
#pragma unroll
        for (int nb = 0; nb < 8; nb++) {
            sacc[nb][0] = ex2f(sacc[nb][0] - mn0);
            sacc[nb][1] = ex2f(sacc[nb][1] - mn0);
            sacc[nb][2] = ex2f(sacc[nb][2] - mn1);
            sacc[nb][3] = ex2f(sacc[nb][3] - mn1);
            sum0 += sacc[nb][0] + sacc[nb][1];
            sum1 += sacc[nb][2] + sacc[nb][3];
        }
        sum0 += __shfl_xor_sync(0xffffffffu, sum0, 1);
        sum0 += __shfl_xor_sync(0xffffffffu, sum0, 2);
        sum1 += __shfl_xor_sync(0xffffffffu, sum1, 1);
        sum1 += __shfl_xor_sync(0xffffffffu, sum1, 2);
        l0 = l0 * al0 + sum0;
        l1 = l1 * al1 + sum1;

#pragma unroll
        for (int nb = 0; nb < 8; nb++) {
            oacc[nb][0] *= al0; oacc[nb][1] *= al0;
            oacc[nb][2] *= al1; oacc[nb][3] *= al1;
        }

        // pack P into A-fragments
        uint32_t pa[4][4];
#pragma unroll
        for (int kb2 = 0; kb2 < 4; kb2++) {
            pa[kb2][0] = h2_bits(__floats2half2_rn(sacc[2 * kb2][0],     sacc[2 * kb2][1]));
            pa[kb2][1] = h2_bits(__floats2half2_rn(sacc[2 * kb2][2],     sacc[2 * kb2][3]));
            pa[kb2][2] = h2_bits(__floats2half2_rn(sacc[2 * kb2 + 1][0], sacc[2 * kb2 + 1][1]));
            pa[kb2][3] = h2_bits(__floats2half2_rn(sacc[2 * kb2 + 1][2], sacc[2 * kb2 + 1][3]));
        }

        // ---- O += P V ----
#pragma unroll
        for (int nbp = 0; nbp < 4; nbp++) {
#pragma unroll
            for (int kb2 = 0; kb2 < 4; kb2++) {
                uint32_t vf[4];
                int row  = 16 * kb2 + (lsel & 1) * 8 + lr;
                int colb = 16 * (2 * nbp + (lsel >> 1));
                ldmatrix_x4_trans(vf, sw_addr(st + ST_V, row, colb));
                mma_16816(oacc[2 * nbp],     pa[kb2], vf[0], vf[1]);
                mma_16816(oacc[2 * nbp + 1], pa[kb2], vf[2], vf[3]);
            }
        }
        // no trailing sync: next iter's entry sync protects stage reuse
    }

    // ---- epilogue: O / l -> gmem ----
    float inv0 = __fdividef(1.f, l0);
    float inv1 = __fdividef(1.f, l1);
    const int row0 = 16 * w + g;
    const int row1 = row0 + 8;
#pragma unroll
    for (int nb = 0; nb < 8; nb++) {
        int col = 8 * nb + 2 * tig;
        *reinterpret_cast<float2*>(og + (size_t)row0 * HDIM + col) =
            make_float2(oacc[nb][0] * inv0, oacc[nb][1] * inv0);
        *reinterpret_cast<float2*>(og + (size_t)row1 * HDIM + col) =
            make_float2(oacc[nb][2] * inv1, oacc[nb][3] * inv1);
    }
}

// ---------------------------------------------------------------------------
extern "C" void kernel_launch(void* const* d_in, const int* in_sizes, int n_in,
                              void* d_out, int out_size) {
    const float* Q = (const float*)d_in[0];
    const float* K = (const float*)d_in[1];
    const float* V = (const float*)d_in[2];
    float* O = (float*)d_out;

    cudaFuncSetAttribute(attn_kernel, cudaFuncAttributeMaxDynamicSharedMemorySize, SMEM_BYTES);

    convert_kernel<<<NTILES, 256>>>(K, V);            // ~30 us pre-pass
    attn_kernel<<<64 * 16, NTHREADS, SMEM_BYTES>>>(Q, O);
}

// round 12
// speedup vs baseline: 1.5414x; 1.2305x over previous
#include <cuda_runtime.h>
#include <cuda_fp16.h>
#include <cstdint>

// ============================================================================
// Attention: softmax(Q K^T) V, B=4 H=16 S=2048 D=64, fp32 in/out.
// FA2-style mma.sync kernel. R9: split kept on Q only —
//   S = (Qhi + Qlo) · fp16(K)^T     (one-sided rounding, pred rel_err ~7e-4)
// K/V pre-converted once per head into pre-swizzled fp16 tiles in scratch;
// attention loop cp.asyncs ready tiles (double-buffered), QK = 64 MMAs/warp.
// ============================================================================

#define DINLINE __device__ __forceinline__

static constexpr int S_LEN = 2048;
static constexpr int HDIM  = 64;
static constexpr int TM    = 128;          // Q rows per CTA
static constexpr int TN    = 64;           // K/V rows per iteration
static constexpr int NIT   = S_LEN / TN;   // 32
static constexpr int NTHREADS = 256;       // 8 warps
static constexpr int NHEADS = 64;
static constexpr int TILE_BYTES = TN * 128;          // 8192 (64 rows x 128B)
static constexpr int NTILES = NHEADS * NIT;          // 2048

// scratch: pre-swizzled fp16 tiles (K, V), 16 MB each
__device__ __align__(16) uint8_t d_kh[(size_t)NTILES * TILE_BYTES];
__device__ __align__(16) uint8_t d_vh[(size_t)NTILES * TILE_BYTES];

// main-kernel dynamic SMEM layout (bytes)
static constexpr int SM_QH = 0;            // 128 x 64 fp16 SW128 (16 KB)
static constexpr int SM_QL = 16384;        // 128 x 64 fp16 SW128 (16 KB)
static constexpr int SM_ST = 32768;        // 2 stages x (K 8K | V 8K)
static constexpr int STAGE = 16384;
static constexpr int ST_V  = 8192;
static constexpr int SMEM_BYTES = SM_ST + 2 * STAGE;   // 64 KB

// ---------------------------------------------------------------------------
DINLINE uint32_t smem_u32(const void* p) {
    uint32_t a;
    asm("{ .reg .u64 t; cvta.to.shared.u64 t, %1; cvt.u32.u64 %0, t; }" : "=r"(a) : "l"(p));
    return a;
}

DINLINE float ex2f(float x) {
    float y;
    asm("ex2.approx.ftz.f32 %0, %1;" : "=f"(y) : "f"(x));
    return y;
}

DINLINE uint32_t h2_bits(__half2 h) {
    uint32_t u;
    __builtin_memcpy(&u, &h, 4);
    return u;
}

DINLINE uint32_t sw_off(int row, int colb) {
    uint32_t off = (uint32_t)(row * 128 + colb);
    return off ^ ((off >> 3) & 0x70);
}

DINLINE uint32_t sw_addr(uint32_t base, int row, int colb) {
    return base + sw_off(row, colb);
}

DINLINE void ldmatrix_x4(uint32_t* r, uint32_t addr) {
    asm volatile("ldmatrix.sync.aligned.m8n8.x4.shared.b16 {%0,%1,%2,%3}, [%4];"
                 : "=r"(r[0]), "=r"(r[1]), "=r"(r[2]), "=r"(r[3]) : "r"(addr));
}

DINLINE void ldmatrix_x4_trans(uint32_t* r, uint32_t addr) {
    asm volatile("ldmatrix.sync.aligned.m8n8.x4.trans.shared.b16 {%0,%1,%2,%3}, [%4];"
                 : "=r"(r[0]), "=r"(r[1]), "=r"(r[2]), "=r"(r[3]) : "r"(addr));
}

DINLINE void mma_16816(float* c, const uint32_t* a, uint32_t b0, uint32_t b1) {
    asm volatile(
        "mma.sync.aligned.m16n8k16.row.col.f32.f16.f16.f32 "
        "{%0,%1,%2,%3}, {%4,%5,%6,%7}, {%8,%9}, {%0,%1,%2,%3};"
        : "+f"(c[0]), "+f"(c[1]), "+f"(c[2]), "+f"(c[3])
        : "r"(a[0]), "r"(a[1]), "r"(a[2]), "r"(a[3]), "r"(b0), "r"(b1));
}

DINLINE void sts_v2(uint32_t addr, uint32_t x, uint32_t y) {
    asm volatile("st.shared.v2.b32 [%0], {%1, %2};" :: "r"(addr), "r"(x), "r"(y) : "memory");
}

// Split-precision pack: hi = fp16(x), lo = fp16(x - hi)
DINLINE void split2(float x, float y, uint32_t& hi, uint32_t& lo) {
    __half hx = __float2half_rn(x);
    __half hy = __float2half_rn(y);
    __half lx = __float2half_rn(x - __half2float(hx));
    __half ly = __float2half_rn(y - __half2float(hy));
    hi = h2_bits(__halves2half2(hx, hy));
    lo = h2_bits(__halves2half2(lx, ly));
}

#define CP_COMMIT() asm volatile("cp.async.commit_group;" ::: "memory")
#define CP_WAIT0()  asm volatile("cp.async.wait_group 0;" ::: "memory")

// cp.async one pre-swizzled 8 KB tile (global scratch -> smem). 2 x 16B/thread.
DINLINE void cp_tile(const uint8_t* __restrict__ g, uint32_t s) {
    const int t = threadIdx.x;
#pragma unroll
    for (int i = 0; i < 2; i++) {
        int idx = t + i * NTHREADS;
        asm volatile("cp.async.cg.shared.global [%0], [%1], 16;"
                     :: "r"(s + idx * 16), "l"(g + idx * 16) : "memory");
    }
}

// ---------------------------------------------------------------------------
// Pre-pass: K/V fp32 -> pre-swizzled fp16 tiles in scratch.
// One block per 64-row tile (tiles are contiguous: tile*4096 floats).
// ---------------------------------------------------------------------------
__global__ void __launch_bounds__(256)
convert_kernel(const float* __restrict__ K, const float* __restrict__ V) {
    const int tile = blockIdx.x;
    const float* kg = K + (size_t)tile * (TN * HDIM);
    const float* vg = V + (size_t)tile * (TN * HDIM);
    uint8_t* okh = d_kh + (size_t)tile * TILE_BYTES;
    uint8_t* ovh = d_vh + (size_t)tile * TILE_BYTES;
    const int t = threadIdx.x;
#pragma unroll
    for (int i = 0; i < 4; i++) {
        int idx = t + i * 256;                 // float4 index, 0..1023
        int row = idx >> 4, c4 = idx & 15;
        uint32_t off = sw_off(row, c4 * 8);
        float4 kv = *reinterpret_cast<const float4*>(kg + idx * 4);
        *reinterpret_cast<uint2*>(okh + off) =
            make_uint2(h2_bits(__floats2half2_rn(kv.x, kv.y)),
                       h2_bits(__floats2half2_rn(kv.z, kv.w)));
        float4 vv = *reinterpret_cast<const float4*>(vg + idx * 4);
        *reinterpret_cast<uint2*>(ovh + off) =
            make_uint2(h2_bits(__floats2half2_rn(vv.x, vv.y)),
                       h2_bits(__floats2half2_rn(vv.z, vv.w)));
    }
}

// Q: direct gmem load -> split fp16 tiles (once per CTA, 128 rows)
DINLINE void load_q_split(const float* __restrict__ g, uint32_t shi, uint32_t slo) {
    const int t = threadIdx.x;
    const float scale = 1.4426950408889634f;   // log2(e)
#pragma unroll
    for (int i = 0; i < 8; i++) {
        int idx = t + i * NTHREADS;
        int row = idx >> 4, c4 = idx & 15;
        float4 v = *reinterpret_cast<const float4*>(g + row * HDIM + c4 * 4);
        uint32_t h0, l0, h1, l1;
        split2(v.x * scale, v.y * scale, h0, l0);
        split2(v.z * scale, v.w * scale, h1, l1);
        sts_v2(sw_addr(shi, row, c4 * 8), h0, h1);
        sts_v2(sw_addr(slo, row, c4 * 8), l0, l1);
    }
}

// ---------------------------------------------------------------------------
__global__ void __launch_bounds__(NTHREADS, 1)
attn_kernel(const float* __restrict__ Q, float* __restrict__ Out) {
    extern __shared__ char smem[];
    const uint32_t sb = smem_u32(smem);

    const int tid = threadIdx.x;
    const int w   = tid >> 5;
    const int lid = tid & 31;
    const int g   = lid >> 2;
    const int tig = lid & 3;

    const int bh = blockIdx.x >> 4;          // head
    const int qt = blockIdx.x & 15;          // Q tile of 128 rows
    const size_t head_off = (size_t)bh * S_LEN * HDIM;
    const float* qg = Q + head_off + (size_t)qt * TM * HDIM;
    float* og = Out + head_off + (size_t)qt * TM * HDIM;
    const size_t tbase = (size_t)bh * NIT;   // first K/V tile of this head

    // ---- prologue: prefetch tile 0, stage Q, build Q frags ----
    cp_tile(d_kh + tbase * TILE_BYTES, sb + SM_ST);
    cp_tile(d_vh + tbase * TILE_BYTES, sb + SM_ST + ST_V);
    CP_COMMIT();

    load_q_split(qg, sb + SM_QH, sb + SM_QL);
    __syncthreads();

    uint32_t qh[4][4], ql[4][4];
    {
        const int r   = lid & 7;
        const int sel = lid >> 3;
        const int row = 16 * w + (sel & 1) * 8 + r;
#pragma unroll
        for (int kb = 0; kb < 4; kb++) {
            int colb = kb * 32 + (sel >> 1) * 16;
            ldmatrix_x4(qh[kb], sw_addr(sb + SM_QH, row, colb));
            ldmatrix_x4(ql[kb], sw_addr(sb + SM_QL, row, colb));
        }
    }

    float oacc[8][4];
#pragma unroll
    for (int nb = 0; nb < 8; nb++)
#pragma unroll
        for (int i = 0; i < 4; i++) oacc[nb][i] = 0.f;

    float m0 = -__int_as_float(0x7f800000), m1 = m0;
    float l0 = 0.f, l1 = 0.f;

    const int lr   = lid & 7;
    const int lsel = lid >> 3;

    for (int j = 0; j < NIT; j++) {
        const uint32_t st = sb + SM_ST + (j & 1) * STAGE;

        // tile j arrived; all warps done reading the other stage (iter j-1)
        CP_WAIT0();
        __syncthreads();

        // prefetch tile j+1 into the other stage (overlaps all MMAs below)
        if (j + 1 < NIT) {
            const uint32_t stn = sb + SM_ST + ((j + 1) & 1) * STAGE;
            const size_t toff = (tbase + j + 1) * TILE_BYTES;
            cp_tile(d_kh + toff, stn);
            cp_tile(d_vh + toff, stn + ST_V);
            CP_COMMIT();
        }

        // ---- S = (Qhi + Qlo) Khi^T : 16 x 64 per warp, 64 MMAs ----
        float sacc[8][4];
#pragma unroll
        for (int nb = 0; nb < 8; nb++) {
#pragma unroll
            for (int i = 0; i < 4; i++) sacc[nb][i] = 0.f;
#pragma unroll
            for (int kbp = 0; kbp < 2; kbp++) {
                uint32_t kh[4];
                int colb = 64 * kbp + lsel * 16;
                ldmatrix_x4(kh, sw_addr(st, 8 * nb + lr, colb));
                mma_16816(sacc[nb], qh[2 * kbp],     kh[0], kh[1]);
                mma_16816(sacc[nb], qh[2 * kbp + 1], kh[2], kh[3]);
                mma_16816(sacc[nb], ql[2 * kbp],     kh[0], kh[1]);
                mma_16816(sacc[nb], ql[2 * kbp + 1], kh[2], kh[3]);
            }
        }

        // ---- online softmax ----
        float mr0 = sacc[0][0], mr1 = sacc[0][2];
#pragma unroll
        for (int nb = 0; nb < 8; nb++) {
            mr0 = fmaxf(mr0, fmaxf(sacc[nb][0], sacc[nb][1]));
            mr1 = fmaxf(mr1, fmaxf(sacc[nb][2], sacc[nb][3]));
        }
        mr0 = fmaxf(mr0, __shfl_xor_sync(0xffffffffu, mr0, 1));
        mr0 = fmaxf(mr0, __shfl_xor_sync(0xffffffffu, mr0, 2));
        mr1 = fmaxf(mr1, __shfl_xor_sync(0xffffffffu, mr1, 1));
        mr1 = fmaxf(mr1, __shfl_xor_sync(0xffffffffu, mr1, 2));

        float mn0 = fmaxf(m0, mr0), mn1 = fmaxf(m1, mr1);
        float al0 = ex2f(m0 - mn0), al1 = ex2f(m1 - mn1);
        m0 = mn0; m1 = mn1;

        float sum0 = 0.f, sum1 = 0.f;
#pragma unroll
        for (int nb = 0; nb < 8; nb++) {
            sacc[nb][0] = ex2f(sacc[nb][0] - mn0);
            sacc[nb][1] = ex2f(sacc[nb][1] - mn0);
            sacc[nb][2] = ex2f(sacc[nb][2] - mn1);
            sacc[nb][3] = ex2f(sacc[nb][3] - mn1);
            sum0 += sacc[nb][0] + sacc[nb][1];
            sum1 += sacc[nb][2] + sacc[nb][3];
        }
        sum0 += __shfl_xor_sync(0xffffffffu, sum0, 1);
        sum0 += __shfl_xor_sync(0xffffffffu, sum0, 2);
        sum1 += __shfl_xor_sync(0xffffffffu, sum1, 1);
        sum1 += __shfl_xor_sync(0xffffffffu, sum1, 2);
        l0 = l0 * al0 + sum0;
        l1 = l1 * al1 + sum1;

#pragma unroll
        for (int nb = 0; nb < 8; nb++) {
            oacc[nb][0] *= al0; oacc[nb][1] *= al0;
            oacc[nb][2] *= al1; oacc[nb][3] *= al1;
        }

        // pack P into A-fragments
        uint32_t pa[4][4];
#pragma unroll
        for (int kb2 = 0; kb2 < 4; kb2++) {
            pa[kb2][0] = h2_bits(__floats2half2_rn(sacc[2 * kb2][0],     sacc[2 * kb2][1]));
            pa[kb2][1] = h2_bits(__floats2half2_rn(sacc[2 * kb2][2],     sacc[2 * kb2][3]));
            pa[kb2][2] = h2_bits(__floats2half2_rn(sacc[2 * kb2 + 1][0], sacc[2 * kb2 + 1][1]));
            pa[kb2][3] = h2_bits(__floats2half2_rn(sacc[2 * kb2 + 1][2], sacc[2 * kb2 + 1][3]));
        }

        // ---- O += P V ----
#pragma unroll
        for (int nbp = 0; nbp < 4; nbp++) {
#pragma unroll
            for (int kb2 = 0; kb2 < 4; kb2++) {
                uint32_t vf[4];
                int row  = 16 * kb2 + (lsel & 1) * 8 + lr;
                int colb = 16 * (2 * nbp + (lsel >> 1));
                ldmatrix_x4_trans(vf, sw_addr(st + ST_V, row, colb));
                mma_16816(oacc[2 * nbp],     pa[kb2], vf[0], vf[1]);
                mma_16816(oacc[2 * nbp + 1], pa[kb2], vf[2], vf[3]);
            }
        }
        // no trailing sync: next iter's entry sync protects stage reuse
    }

    // ---- epilogue: O / l -> gmem ----
    float inv0 = __fdividef(1.f, l0);
    float inv1 = __fdividef(1.f, l1);
    const int row0 = 16 * w + g;
    const int row1 = row0 + 8;
#pragma unroll
    for (int nb = 0; nb < 8; nb++) {
        int col = 8 * nb + 2 * tig;
        *reinterpret_cast<float2*>(og + (size_t)row0 * HDIM + col) =
            make_float2(oacc[nb][0] * inv0, oacc[nb][1] * inv0);
        *reinterpret_cast<float2*>(og + (size_t)row1 * HDIM + col) =
            make_float2(oacc[nb][2] * inv1, oacc[nb][3] * inv1);
    }
}

// ---------------------------------------------------------------------------
extern "C" void kernel_launch(void* const* d_in, const int* in_sizes, int n_in,
                              void* d_out, int out_size) {
    const float* Q = (const float*)d_in[0];
    const float* K = (const float*)d_in[1];
    const float* V = (const float*)d_in[2];
    float* O = (float*)d_out;

    cudaFuncSetAttribute(attn_kernel, cudaFuncAttributeMaxDynamicSharedMemorySize, SMEM_BYTES);

    convert_kernel<<<NTILES, 256>>>(K, V);            // ~15 us pre-pass
    attn_kernel<<<64 * 16, NTHREADS, SMEM_BYTES>>>(Q, O);
}

// round 13
// speedup vs baseline: 1.6433x; 1.0661x over previous
#include <cuda_runtime.h>
#include <cuda_fp16.h>
#include <cstdint>

// ============================================================================
// Attention: softmax(Q K^T) V, B=4 H=16 S=2048 D=64, fp32 in/out.
// FA2-style mma.sync kernel. S = (Qhi + Qlo) · fp16(K)^T (rel_err ~8e-4).
// K/V pre-converted once into pre-swizzled fp16 tiles (scratch); loop
// cp.asyncs ready tiles (double-buffered).
// R10: TM 128->64, 128 threads, 2 CTAs/SM — independent barrier domains per
// SMSP so one CTA's softmax overlaps the other's MMAs. (R7 retried: the
// duplicated-convert cost that sank it is gone since R9.)
// ============================================================================

#define DINLINE __device__ __forceinline__

static constexpr int S_LEN = 2048;
static constexpr int HDIM  = 64;
static constexpr int TM    = 64;           // Q rows per CTA
static constexpr int TN    = 64;           // K/V rows per iteration
static constexpr int NIT   = S_LEN / TN;   // 32
static constexpr int NTHREADS = 128;       // 4 warps
static constexpr int NQT   = S_LEN / TM;   // 32 Q tiles per head
static constexpr int NHEADS = 64;
static constexpr int TILE_BYTES = TN * 128;          // 8192 (64 rows x 128B)
static constexpr int NTILES = NHEADS * NIT;          // 2048

// scratch: pre-swizzled fp16 tiles (K, V), 16 MB each
__device__ __align__(16) uint8_t d_kh[(size_t)NTILES * TILE_BYTES];
__device__ __align__(16) uint8_t d_vh[(size_t)NTILES * TILE_BYTES];

// main-kernel dynamic SMEM layout (bytes)
static constexpr int SM_QH = 0;            // 64 x 64 fp16 SW128 (8 KB)
static constexpr int SM_QL = 8192;         // 64 x 64 fp16 SW128 (8 KB)
static constexpr int SM_ST = 16384;        // 2 stages x (K 8K | V 8K)
static constexpr int STAGE = 16384;
static constexpr int ST_V  = 8192;
static constexpr int SMEM_BYTES = SM_ST + 2 * STAGE;   // 48 KB

// ---------------------------------------------------------------------------
DINLINE uint32_t smem_u32(const void* p) {
    uint32_t a;
    asm("{ .reg .u64 t; cvta.to.shared.u64 t, %1; cvt.u32.u64 %0, t; }" : "=r"(a) : "l"(p));
    return a;
}

DINLINE float ex2f(float x) {
    float y;
    asm("ex2.approx.ftz.f32 %0, %1;" : "=f"(y) : "f"(x));
    return y;
}

DINLINE uint32_t h2_bits(__half2 h) {
    uint32_t u;
    __builtin_memcpy(&u, &h, 4);
    return u;
}

DINLINE uint32_t sw_off(int row, int colb) {
    uint32_t off = (uint32_t)(row * 128 + colb);
    return off ^ ((off >> 3) & 0x70);
}

DINLINE uint32_t sw_addr(uint32_t base, int row, int colb) {
    return base + sw_off(row, colb);
}

DINLINE void ldmatrix_x4(uint32_t* r, uint32_t addr) {
    asm volatile("ldmatrix.sync.aligned.m8n8.x4.shared.b16 {%0,%1,%2,%3}, [%4];"
                 : "=r"(r[0]), "=r"(r[1]), "=r"(r[2]), "=r"(r[3]) : "r"(addr));
}

DINLINE void ldmatrix_x4_trans(uint32_t* r, uint32_t addr) {
    asm volatile("ldmatrix.sync.aligned.m8n8.x4.trans.shared.b16 {%0,%1,%2,%3}, [%4];"
                 : "=r"(r[0]), "=r"(r[1]), "=r"(r[2]), "=r"(r[3]) : "r"(addr));
}

DINLINE void mma_16816(float* c, const uint32_t* a, uint32_t b0, uint32_t b1) {
    asm volatile(
        "mma.sync.aligned.m16n8k16.row.col.f32.f16.f16.f32 "
        "{%0,%1,%2,%3}, {%4,%5,%6,%7}, {%8,%9}, {%0,%1,%2,%3};"
        : "+f"(c[0]), "+f"(c[1]), "+f"(c[2]), "+f"(c[3])
        : "r"(a[0]), "r"(a[1]), "r"(a[2]), "r"(a[3]), "r"(b0), "r"(b1));
}

DINLINE void sts_v2(uint32_t addr, uint32_t x, uint32_t y) {
    asm volatile("st.shared.v2.b32 [%0], {%1, %2};" :: "r"(addr), "r"(x), "r"(y) : "memory");
}

// Split-precision pack: hi = fp16(x), lo = fp16(x - hi)
DINLINE void split2(float x, float y, uint32_t& hi, uint32_t& lo) {
    __half hx = __float2half_rn(x);
    __half hy = __float2half_rn(y);
    __half lx = __float2half_rn(x - __half2float(hx));
    __half ly = __float2half_rn(y - __half2float(hy));
    hi = h2_bits(__halves2half2(hx, hy));
    lo = h2_bits(__halves2half2(lx, ly));
}

#define CP_COMMIT() asm volatile("cp.async.commit_group;" ::: "memory")
#define CP_WAIT0()  asm volatile("cp.async.wait_group 0;" ::: "memory")

// cp.async one pre-swizzled 8 KB tile (global scratch -> smem). 4 x 16B/thread.
DINLINE void cp_tile(const uint8_t* __restrict__ g, uint32_t s) {
    const int t = threadIdx.x;
#pragma unroll
    for (int i = 0; i < 4; i++) {
        int idx = t + i * NTHREADS;
        asm volatile("cp.async.cg.shared.global [%0], [%1], 16;"
                     :: "r"(s + idx * 16), "l"(g + idx * 16) : "memory");
    }
}

// ---------------------------------------------------------------------------
// Pre-pass: K/V fp32 -> pre-swizzled fp16 tiles in scratch.
// One block per 64-row tile (tiles are contiguous: tile*4096 floats).
// ---------------------------------------------------------------------------
__global__ void __launch_bounds__(256)
convert_kernel(const float* __restrict__ K, const float* __restrict__ V) {
    const int tile = blockIdx.x;
    const float* kg = K + (size_t)tile * (TN * HDIM);
    const float* vg = V + (size_t)tile * (TN * HDIM);
    uint8_t* okh = d_kh + (size_t)tile * TILE_BYTES;
    uint8_t* ovh = d_vh + (size_t)tile * TILE_BYTES;
    const int t = threadIdx.x;
#pragma unroll
    for (int i = 0; i < 4; i++) {
        int idx = t + i * 256;                 // float4 index, 0..1023
        int row = idx >> 4, c4 = idx & 15;
        uint32_t off = sw_off(row, c4 * 8);
        float4 kv = *reinterpret_cast<const float4*>(kg + idx * 4);
        *reinterpret_cast<uint2*>(okh + off) =
            make_uint2(h2_bits(__floats2half2_rn(kv.x, kv.y)),
                       h2_bits(__floats2half2_rn(kv.z, kv.w)));
        float4 vv = *reinterpret_cast<const float4*>(vg + idx * 4);
        *reinterpret_cast<uint2*>(ovh + off) =
            make_uint2(h2_bits(__floats2half2_rn(vv.x, vv.y)),
                       h2_bits(__floats2half2_rn(vv.z, vv.w)));
    }
}

// Q: direct gmem load -> split fp16 tiles (once per CTA, 64 rows)
DINLINE void load_q_split(const float* __restrict__ g, uint32_t shi, uint32_t slo) {
    const int t = threadIdx.x;
    const float scale = 1.4426950408889634f;   // log2(e)
#pragma unroll
    for (int i = 0; i < 8; i++) {
        int idx = t + i * NTHREADS;            // 0..1023 float4s (64 rows x 16)
        int row = idx >> 4, c4 = idx & 15;
        float4 v = *reinterpret_cast<const float4*>(g + row * HDIM + c4 * 4);
        uint32_t h0, l0, h1, l1;
        split2(v.x * scale, v.y * scale, h0, l0);
        split2(v.z * scale, v.w * scale, h1, l1);
        sts_v2(sw_addr(shi, row, c4 * 8), h0, h1);
        sts_v2(sw_addr(slo, row, c4 * 8), l0, l1);
    }
}

// ---------------------------------------------------------------------------
__global__ void __launch_bounds__(NTHREADS, 2)
attn_kernel(const float* __restrict__ Q, float* __restrict__ Out) {
    extern __shared__ char smem[];
    const uint32_t sb = smem_u32(smem);

    const int tid = threadIdx.x;
    const int w   = tid >> 5;        // 0..3
    const int lid = tid & 31;
    const int g   = lid >> 2;
    const int tig = lid & 3;

    const int bh = blockIdx.x >> 5;          // head (64)
    const int qt = blockIdx.x & 31;          // Q tile of 64 rows (32)
    const size_t head_off = (size_t)bh * S_LEN * HDIM;
    const float* qg = Q + head_off + (size_t)qt * TM * HDIM;
    float* og = Out + head_off + (size_t)qt * TM * HDIM;
    const size_t tbase = (size_t)bh * NIT;   // first K/V tile of this head

    // ---- prologue: prefetch tile 0, stage Q, build Q frags ----
    cp_tile(d_kh + tbase * TILE_BYTES, sb + SM_ST);
    cp_tile(d_vh + tbase * TILE_BYTES, sb + SM_ST + ST_V);
    CP_COMMIT();

    load_q_split(qg, sb + SM_QH, sb + SM_QL);
    __syncthreads();

    uint32_t qh[4][4], ql[4][4];
    {
        const int r   = lid & 7;
        const int sel = lid >> 3;
        const int row = 16 * w + (sel & 1) * 8 + r;
#pragma unroll
        for (int kb = 0; kb < 4; kb++) {
            int colb = kb * 32 + (sel >> 1) * 16;
            ldmatrix_x4(qh[kb], sw_addr(sb + SM_QH, row, colb));
            ldmatrix_x4(ql[kb], sw_addr(sb + SM_QL, row, colb));
        }
    }

    float oacc[8][4];
#pragma unroll
    for (int nb = 0; nb < 8; nb++)
#pragma unroll
        for (int i = 0; i < 4; i++) oacc[nb][i] = 0.f;

    float m0 = -__int_as_float(0x7f800000), m1 = m0;
    float l0 = 0.f, l1 = 0.f;

    const int lr   = lid & 7;
    const int lsel = lid >> 3;

    for (int j = 0; j < NIT; j++) {
        const uint32_t st = sb + SM_ST + (j & 1) * STAGE;

        // tile j arrived; all warps done reading the other stage (iter j-1)
        CP_WAIT0();
        __syncthreads();

        // prefetch tile j+1 into the other stage (overlaps all MMAs below)
        if (j + 1 < NIT) {
            const uint32_t stn = sb + SM_ST + ((j + 1) & 1) * STAGE;
            const size_t toff = (tbase + j + 1) * TILE_BYTES;
            cp_tile(d_kh + toff, stn);
            cp_tile(d_vh + toff, stn + ST_V);
            CP_COMMIT();
        }

        // ---- S = (Qhi + Qlo) Khi^T : 16 x 64 per warp, 64 MMAs ----
        float sacc[8][4];
#pragma unroll
        for (int nb = 0; nb < 8; nb++) {
#pragma unroll
            for (int i = 0; i < 4; i++) sacc[nb][i] = 0.f;
#pragma unroll
            for (int kbp = 0; kbp < 2; kbp++) {
                uint32_t kh[4];
                int colb = 64 * kbp + lsel * 16;
                ldmatrix_x4(kh, sw_addr(st, 8 * nb + lr, colb));
                mma_16816(sacc[nb], qh[2 * kbp],     kh[0], kh[1]);
                mma_16816(sacc[nb], qh[2 * kbp + 1], kh[2], kh[3]);
                mma_16816(sacc[nb], ql[2 * kbp],     kh[0], kh[1]);
                mma_16816(sacc[nb], ql[2 * kbp + 1], kh[2], kh[3]);
            }
        }

        // ---- online softmax ----
        float mr0 = sacc[0][0], mr1 = sacc[0][2];
#pragma unroll
        for (int nb = 0; nb < 8; nb++) {
            mr0 = fmaxf(mr0, fmaxf(sacc[nb][0], sacc[nb][1]));
            mr1 = fmaxf(mr1, fmaxf(sacc[nb][2], sacc[nb][3]));
        }
        mr0 = fmaxf(mr0, __shfl_xor_sync(0xffffffffu, mr0, 1));
        mr0 = fmaxf(mr0, __shfl_xor_sync(0xffffffffu, mr0, 2));
        mr1 = fmaxf(mr1, __shfl_xor_sync(0xffffffffu, mr1, 1));
        mr1 = fmaxf(mr1, __shfl_xor_sync(0xffffffffu, mr1, 2));

        float mn0 = fmaxf(m0, mr0), mn1 = fmaxf(m1, mr1);
        float al0 = ex2f(m0 - mn0), al1 = ex2f(m1 - mn1);
        m0 = mn0; m1 = mn1;

        float sum0 = 0.f, sum1 = 0.f;
#pragma unroll
        for (int nb = 0; nb < 8; nb++) {
            sacc[nb][0] = ex2f(sacc[nb][0] - mn0);
            sacc[nb][1] = ex2f(sacc[nb][1] - mn0);
            sacc[nb][2] = ex2f(sacc[nb][2] - mn1);
            sacc[nb][3] = ex2f(sacc[nb][3] - mn1);
            sum0 += sacc[nb][0] + sacc[nb][1];
            sum1 += sacc[nb][2] + sacc[nb][3];
        }
        sum0 += __shfl_xor_sync(0xffffffffu, sum0, 1);
        sum0 += __shfl_xor_sync(0xffffffffu, sum0, 2);
        sum1 += __shfl_xor_sync(0xffffffffu, sum1, 1);
        sum1 += __shfl_xor_sync(0xffffffffu, sum1, 2);
        l0 = l0 * al0 + sum0;
        l1 = l1 * al1 + sum1;

#pragma unroll
        for (int nb = 0; nb < 8; nb++) {
            oacc[nb][0] *= al0; oacc[nb][1] *= al0;
            oacc[nb][2] *= al1; oacc[nb][3] *= al1;
        }

        // pack P into A-fragments
        uint32_t pa[4][4];
#pragma unroll
        for (int kb2 = 0; kb2 < 4; kb2++) {
            pa[kb2][0] = h2_bits(__floats2half2_rn(sacc[2 * kb2][0],     sacc[2 * kb2][1]));
            pa[kb2][1] = h2_bits(__floats2half2_rn(sacc[2 * kb2][2],     sacc[2 * kb2][3]));
            pa[kb2][2] = h2_bits(__floats2half2_rn(sacc[2 * kb2 + 1][0], sacc[2 * kb2 + 1][1]));
            pa[kb2][3] = h2_bits(__floats2half2_rn(sacc[2 * kb2 + 1][2], sacc[2 * kb2 + 1][3]));
        }

        // ---- O += P V ----
#pragma unroll
        for (int nbp = 0; nbp < 4; nbp++) {
#pragma unroll
            for (int kb2 = 0; kb2 < 4; kb2++) {
                uint32_t vf[4];
                int row  = 16 * kb2 + (lsel & 1) * 8 + lr;
                int colb = 16 * (2 * nbp + (lsel >> 1));
                ldmatrix_x4_trans(vf, sw_addr(st + ST_V, row, colb));
                mma_16816(oacc[2 * nbp],     pa[kb2], vf[0], vf[1]);
                mma_16816(oacc[2 * nbp + 1], pa[kb2], vf[2], vf[3]);
            }
        }
        // no trailing sync: next iter's entry sync protects stage reuse
    }

    // ---- epilogue: O / l -> gmem ----
    float inv0 = __fdividef(1.f, l0);
    float inv1 = __fdividef(1.f, l1);
    const int row0 = 16 * w + g;
    const int row1 = row0 + 8;
#pragma unroll
    for (int nb = 0; nb < 8; nb++) {
        int col = 8 * nb + 2 * tig;
        *reinterpret_cast<float2*>(og + (size_t)row0 * HDIM + col) =
            make_float2(oacc[nb][0] * inv0, oacc[nb][1] * inv0);
        *reinterpret_cast<float2*>(og + (size_t)row1 * HDIM + col) =
            make_float2(oacc[nb][2] * inv1, oacc[nb][3] * inv1);
    }
}

// ---------------------------------------------------------------------------
extern "C" void kernel_launch(void* const* d_in, const int* in_sizes, int n_in,
                              void* d_out, int out_size) {
    const float* Q = (const float*)d_in[0];
    const float* K = (const float*)d_in[1];
    const float* V = (const float*)d_in[2];
    float* O = (float*)d_out;

    cudaFuncSetAttribute(attn_kernel, cudaFuncAttributeMaxDynamicSharedMemorySize, SMEM_BYTES);

    convert_kernel<<<NTILES, 256>>>(K, V);            // ~15 us pre-pass
    attn_kernel<<<64 * NQT, NTHREADS, SMEM_BYTES>>>(Q, O);
}

// round 14
// speedup vs baseline: 1.7075x; 1.0390x over previous
#include <cuda_runtime.h>
#include <cuda_fp16.h>
#include <cstdint>

// ============================================================================
// Attention: softmax(Q K^T) V, B=4 H=16 S=2048 D=64, fp32 in/out.
// FA2-style mma.sync kernel. S = (Qhi + Qlo) · fp16(K)^T.
// K/V pre-converted once into pre-swizzled fp16 tiles (scratch); loop
// cp.asyncs ready tiles (double-buffered). TM=64, 2 CTAs/SM.
// R11: softmax diet — ex2.approx.f16x2 produces P fragments directly
// (MUFU ops halved), and row sums l come from 4 MMAs against a ones-B
// fragment (fp32 accum of the actual fp16 P; no FADD/shfl reduction).
// ============================================================================

#define DINLINE __device__ __forceinline__

static constexpr int S_LEN = 2048;
static constexpr int HDIM  = 64;
static constexpr int TM    = 64;           // Q rows per CTA
static constexpr int TN    = 64;           // K/V rows per iteration
static constexpr int NIT   = S_LEN / TN;   // 32
static constexpr int NTHREADS = 128;       // 4 warps
static constexpr int NQT   = S_LEN / TM;   // 32 Q tiles per head
static constexpr int NHEADS = 64;
static constexpr int TILE_BYTES = TN * 128;          // 8192 (64 rows x 128B)
static constexpr int NTILES = NHEADS * NIT;          // 2048
static constexpr uint32_t ONES2 = 0x3C003C00u;       // half2(1,1)

// scratch: pre-swizzled fp16 tiles (K, V), 16 MB each
__device__ __align__(16) uint8_t d_kh[(size_t)NTILES * TILE_BYTES];
__device__ __align__(16) uint8_t d_vh[(size_t)NTILES * TILE_BYTES];

// main-kernel dynamic SMEM layout (bytes)
static constexpr int SM_QH = 0;            // 64 x 64 fp16 SW128 (8 KB)
static constexpr int SM_QL = 8192;         // 64 x 64 fp16 SW128 (8 KB)
static constexpr int SM_ST = 16384;        // 2 stages x (K 8K | V 8K)
static constexpr int STAGE = 16384;
static constexpr int ST_V  = 8192;
static constexpr int SMEM_BYTES = SM_ST + 2 * STAGE;   // 48 KB

// ---------------------------------------------------------------------------
DINLINE uint32_t smem_u32(const void* p) {
    uint32_t a;
    asm("{ .reg .u64 t; cvta.to.shared.u64 t, %1; cvt.u32.u64 %0, t; }" : "=r"(a) : "l"(p));
    return a;
}

DINLINE float ex2f(float x) {
    float y;
    asm("ex2.approx.ftz.f32 %0, %1;" : "=f"(y) : "f"(x));
    return y;
}

// packed fp16 exp2: one MUFU op for two values
DINLINE uint32_t ex2h2(uint32_t a) {
    uint32_t y;
    asm("ex2.approx.f16x2 %0, %1;" : "=r"(y) : "r"(a));
    return y;
}

DINLINE uint32_t h2_bits(__half2 h) {
    uint32_t u;
    __builtin_memcpy(&u, &h, 4);
    return u;
}

DINLINE uint32_t sw_off(int row, int colb) {
    uint32_t off = (uint32_t)(row * 128 + colb);
    return off ^ ((off >> 3) & 0x70);
}

DINLINE uint32_t sw_addr(uint32_t base, int row, int colb) {
    return base + sw_off(row, colb);
}

DINLINE void ldmatrix_x4(uint32_t* r, uint32_t addr) {
    asm volatile("ldmatrix.sync.aligned.m8n8.x4.shared.b16 {%0,%1,%2,%3}, [%4];"
                 : "=r"(r[0]), "=r"(r[1]), "=r"(r[2]), "=r"(r[3]) : "r"(addr));
}

DINLINE void ldmatrix_x4_trans(uint32_t* r, uint32_t addr) {
    asm volatile("ldmatrix.sync.aligned.m8n8.x4.trans.shared.b16 {%0,%1,%2,%3}, [%4];"
                 : "=r"(r[0]), "=r"(r[1]), "=r"(r[2]), "=r"(r[3]) : "r"(addr));
}

DINLINE void mma_16816(float* c, const uint32_t* a, uint32_t b0, uint32_t b1) {
    asm volatile(
        "mma.sync.aligned.m16n8k16.row.col.f32.f16.f16.f32 "
        "{%0,%1,%2,%3}, {%4,%5,%6,%7}, {%8,%9}, {%0,%1,%2,%3};"
        : "+f"(c[0]), "+f"(c[1]), "+f"(c[2]), "+f"(c[3])
        : "r"(a[0]), "r"(a[1]), "r"(a[2]), "r"(a[3]), "r"(b0), "r"(b1));
}

DINLINE void sts_v2(uint32_t addr, uint32_t x, uint32_t y) {
    asm volatile("st.shared.v2.b32 [%0], {%1, %2};" :: "r"(addr), "r"(x), "r"(y) : "memory");
}

// Split-precision pack: hi = fp16(x), lo = fp16(x - hi)
DINLINE void split2(float x, float y, uint32_t& hi, uint32_t& lo) {
    __half hx = __float2half_rn(x);
    __half hy = __float2half_rn(y);
    __half lx = __float2half_rn(x - __half2float(hx));
    __half ly = __float2half_rn(y - __half2float(hy));
    hi = h2_bits(__halves2half2(hx, hy));
    lo = h2_bits(__halves2half2(lx, ly));
}

#define CP_COMMIT() asm volatile("cp.async.commit_group;" ::: "memory")
#define CP_WAIT0()  asm volatile("cp.async.wait_group 0;" ::: "memory")

// cp.async one pre-swizzled 8 KB tile (global scratch -> smem). 4 x 16B/thread.
DINLINE void cp_tile(const uint8_t* __restrict__ g, uint32_t s) {
    const int t = threadIdx.x;
#pragma unroll
    for (int i = 0; i < 4; i++) {
        int idx = t + i * NTHREADS;
        asm volatile("cp.async.cg.shared.global [%0], [%1], 16;"
                     :: "r"(s + idx * 16), "l"(g + idx * 16) : "memory");
    }
}

// ---------------------------------------------------------------------------
// Pre-pass: K/V fp32 -> pre-swizzled fp16 tiles in scratch.
// ---------------------------------------------------------------------------
__global__ void __launch_bounds__(256)
convert_kernel(const float* __restrict__ K, const float* __restrict__ V) {
    const int tile = blockIdx.x;
    const float* kg = K + (size_t)tile * (TN * HDIM);
    const float* vg = V + (size_t)tile * (TN * HDIM);
    uint8_t* okh = d_kh + (size_t)tile * TILE_BYTES;
    uint8_t* ovh = d_vh + (size_t)tile * TILE_BYTES;
    const int t = threadIdx.x;
#pragma unroll
    for (int i = 0; i < 4; i++) {
        int idx = t + i * 256;                 // float4 index, 0..1023
        int row = idx >> 4, c4 = idx & 15;
        uint32_t off = sw_off(row, c4 * 8);
        float4 kv = *reinterpret_cast<const float4*>(kg + idx * 4);
        *reinterpret_cast<uint2*>(okh + off) =
            make_uint2(h2_bits(__floats2half2_rn(kv.x, kv.y)),
                       h2_bits(__floats2half2_rn(kv.z, kv.w)));
        float4 vv = *reinterpret_cast<const float4*>(vg + idx * 4);
        *reinterpret_cast<uint2*>(ovh + off) =
            make_uint2(h2_bits(__floats2half2_rn(vv.x, vv.y)),
                       h2_bits(__floats2half2_rn(vv.z, vv.w)));
    }
}

// Q: direct gmem load -> split fp16 tiles (once per CTA, 64 rows)
DINLINE void load_q_split(const float* __restrict__ g, uint32_t shi, uint32_t slo) {
    const int t = threadIdx.x;
    const float scale = 1.4426950408889634f;   // log2(e)
#pragma unroll
    for (int i = 0; i < 8; i++) {
        int idx = t + i * NTHREADS;            // 0..1023 float4s (64 rows x 16)
        int row = idx >> 4, c4 = idx & 15;
        float4 v = *reinterpret_cast<const float4*>(g + row * HDIM + c4 * 4);
        uint32_t h0, l0, h1, l1;
        split2(v.x * scale, v.y * scale, h0, l0);
        split2(v.z * scale, v.w * scale, h1, l1);
        sts_v2(sw_addr(shi, row, c4 * 8), h0, h1);
        sts_v2(sw_addr(slo, row, c4 * 8), l0, l1);
    }
}

// ---------------------------------------------------------------------------
__global__ void __launch_bounds__(NTHREADS, 2)
attn_kernel(const float* __restrict__ Q, float* __restrict__ Out) {
    extern __shared__ char smem[];
    const uint32_t sb = smem_u32(smem);

    const int tid = threadIdx.x;
    const int w   = tid >> 5;        // 0..3
    const int lid = tid & 31;
    const int g   = lid >> 2;
    const int tig = lid & 3;

    const int bh = blockIdx.x >> 5;          // head (64)
    const int qt = blockIdx.x & 31;          // Q tile of 64 rows (32)
    const size_t head_off = (size_t)bh * S_LEN * HDIM;
    const float* qg = Q + head_off + (size_t)qt * TM * HDIM;
    float* og = Out + head_off + (size_t)qt * TM * HDIM;
    const size_t tbase = (size_t)bh * NIT;   // first K/V tile of this head

    // ---- prologue: prefetch tile 0, stage Q, build Q frags ----
    cp_tile(d_kh + tbase * TILE_BYTES, sb + SM_ST);
    cp_tile(d_vh + tbase * TILE_BYTES, sb + SM_ST + ST_V);
    CP_COMMIT();

    load_q_split(qg, sb + SM_QH, sb + SM_QL);
    __syncthreads();

    uint32_t qh[4][4], ql[4][4];
    {
        const int r   = lid & 7;
        const int sel = lid >> 3;
        const int row = 16 * w + (sel & 1) * 8 + r;
#pragma unroll
        for (int kb = 0; kb < 4; kb++) {
            int colb = kb * 32 + (sel >> 1) * 16;
            ldmatrix_x4(qh[kb], sw_addr(sb + SM_QH, row, colb));
            ldmatrix_x4(ql[kb], sw_addr(sb + SM_QL, row, colb));
        }
    }

    float oacc[8][4];
#pragma unroll
    for (int nb = 0; nb < 8; nb++)
#pragma unroll
        for (int i = 0; i < 4; i++) oacc[nb][i] = 0.f;

    float m0 = -__int_as_float(0x7f800000), m1 = m0;
    float l0 = 0.f, l1 = 0.f;

    const int lr   = lid & 7;
    const int lsel = lid >> 3;

    for (int j = 0; j < NIT; j++) {
        const uint32_t st = sb + SM_ST + (j & 1) * STAGE;

        // tile j arrived; all warps done reading the other stage (iter j-1)
        CP_WAIT0();
        __syncthreads();

        // prefetch tile j+1 into the other stage (overlaps all MMAs below)
        if (j + 1 < NIT) {
            const uint32_t stn = sb + SM_ST + ((j + 1) & 1) * STAGE;
            const size_t toff = (tbase + j + 1) * TILE_BYTES;
            cp_tile(d_kh + toff, stn);
            cp_tile(d_vh + toff, stn + ST_V);
            CP_COMMIT();
        }

        // ---- S = (Qhi + Qlo) Khi^T : 16 x 64 per warp, 64 MMAs ----
        float sacc[8][4];
#pragma unroll
        for (int nb = 0; nb < 8; nb++) {
#pragma unroll
            for (int i = 0; i < 4; i++) sacc[nb][i] = 0.f;
#pragma unroll
            for (int kbp = 0; kbp < 2; kbp++) {
                uint32_t kh[4];
                int colb = 64 * kbp + lsel * 16;
                ldmatrix_x4(kh, sw_addr(st, 8 * nb + lr, colb));
                mma_16816(sacc[nb], qh[2 * kbp],     kh[0], kh[1]);
                mma_16816(sacc[nb], qh[2 * kbp + 1], kh[2], kh[3]);
                mma_16816(sacc[nb], ql[2 * kbp],     kh[0], kh[1]);
                mma_16816(sacc[nb], ql[2 * kbp + 1], kh[2], kh[3]);
            }
        }

        // ---- online softmax: row max (fp32) ----
        float mr0 = sacc[0][0], mr1 = sacc[0][2];
#pragma unroll
        for (int nb = 0; nb < 8; nb++) {
            mr0 = fmaxf(mr0, fmaxf(sacc[nb][0], sacc[nb][1]));
            mr1 = fmaxf(mr1, fmaxf(sacc[nb][2], sacc[nb][3]));
        }
        mr0 = fmaxf(mr0, __shfl_xor_sync(0xffffffffu, mr0, 1));
        mr0 = fmaxf(mr0, __shfl_xor_sync(0xffffffffu, mr0, 2));
        mr1 = fmaxf(mr1, __shfl_xor_sync(0xffffffffu, mr1, 1));
        mr1 = fmaxf(mr1, __shfl_xor_sync(0xffffffffu, mr1, 2));

        float mn0 = fmaxf(m0, mr0), mn1 = fmaxf(m1, mr1);
        float al0 = ex2f(m0 - mn0), al1 = ex2f(m1 - mn1);
        m0 = mn0; m1 = mn1;

        // ---- P = exp2(s - mn) directly in packed fp16 (A-fragments) ----
        uint32_t pa[4][4];
#pragma unroll
        for (int kb2 = 0; kb2 < 4; kb2++) {
            pa[kb2][0] = ex2h2(h2_bits(__floats2half2_rn(sacc[2 * kb2][0] - mn0,
                                                         sacc[2 * kb2][1] - mn0)));
            pa[kb2][1] = ex2h2(h2_bits(__floats2half2_rn(sacc[2 * kb2][2] - mn1,
                                                         sacc[2 * kb2][3] - mn1)));
            pa[kb2][2] = ex2h2(h2_bits(__floats2half2_rn(sacc[2 * kb2 + 1][0] - mn0,
                                                         sacc[2 * kb2 + 1][1] - mn0)));
            pa[kb2][3] = ex2h2(h2_bits(__floats2half2_rn(sacc[2 * kb2 + 1][2] - mn1,
                                                         sacc[2 * kb2 + 1][3] - mn1)));
        }

        // ---- row sums via MMA against ones (fp32 accum of actual fp16 P) ----
        float sumacc[4] = {0.f, 0.f, 0.f, 0.f};
#pragma unroll
        for (int kb2 = 0; kb2 < 4; kb2++)
            mma_16816(sumacc, pa[kb2], ONES2, ONES2);
        l0 = l0 * al0 + sumacc[0];
        l1 = l1 * al1 + sumacc[2];

        // ---- rescale O accum ----
#pragma unroll
        for (int nb = 0; nb < 8; nb++) {
            oacc[nb][0] *= al0; oacc[nb][1] *= al0;
            oacc[nb][2] *= al1; oacc[nb][3] *= al1;
        }

        // ---- O += P V ----
#pragma unroll
        for (int nbp = 0; nbp < 4; nbp++) {
#pragma unroll
            for (int kb2 = 0; kb2 < 4; kb2++) {
                uint32_t vf[4];
                int row  = 16 * kb2 + (lsel & 1) * 8 + lr;
                int colb = 16 * (2 * nbp + (lsel >> 1));
                ldmatrix_x4_trans(vf, sw_addr(st + ST_V, row, colb));
                mma_16816(oacc[2 * nbp],     pa[kb2], vf[0], vf[1]);
                mma_16816(oacc[2 * nbp + 1], pa[kb2], vf[2], vf[3]);
            }
        }
        // no trailing sync: next iter's entry sync protects stage reuse
    }

    // ---- epilogue: O / l -> gmem ----
    float inv0 = __fdividef(1.f, l0);
    float inv1 = __fdividef(1.f, l1);
    const int row0 = 16 * w + g;
    const int row1 = row0 + 8;
#pragma unroll
    for (int nb = 0; nb < 8; nb++) {
        int col = 8 * nb + 2 * tig;
        *reinterpret_cast<float2*>(og + (size_t)row0 * HDIM + col) =
            make_float2(oacc[nb][0] * inv0, oacc[nb][1] * inv0);
        *reinterpret_cast<float2*>(og + (size_t)row1 * HDIM + col) =
            make_float2(oacc[nb][2] * inv1, oacc[nb][3] * inv1);
    }
}

// ---------------------------------------------------------------------------
extern "C" void kernel_launch(void* const* d_in, const int* in_sizes, int n_in,
                              void* d_out, int out_size) {
    const float* Q = (const float*)d_in[0];
    const float* K = (const float*)d_in[1];
    const float* V = (const float*)d_in[2];
    float* O = (float*)d_out;

    cudaFuncSetAttribute(attn_kernel, cudaFuncAttributeMaxDynamicSharedMemorySize, SMEM_BYTES);

    convert_kernel<<<NTILES, 256>>>(K, V);            // ~15 us pre-pass
    attn_kernel<<<64 * NQT, NTHREADS, SMEM_BYTES>>>(Q, O);
}

// round 15
// speedup vs baseline: 1.7077x; 1.0001x over previous
#include <cuda_runtime.h>
#include <cuda_fp16.h>
#include <cstdint>

// ============================================================================
// Attention: softmax(Q K^T) V, B=4 H=16 S=2048 D=64, fp32 in/out.
// FA2-style mma.sync kernel. S = (Qhi + Qlo) · fp16(K)^T (rel_err ~8e-4).
// K/V pre-converted once into pre-swizzled fp16 tiles (scratch); loop
// cp.asyncs ready tiles (double-buffered). ex2.f16x2 softmax, MMA row-sums.
// R12: 3 CTAs/SM (__launch_bounds__(128,3), 170-reg cap) — a third
// independent barrier domain per SMSP to hide the softmax dependency chain.
// ============================================================================

#define DINLINE __device__ __forceinline__

static constexpr int S_LEN = 2048;
static constexpr int HDIM  = 64;
static constexpr int TM    = 64;           // Q rows per CTA
static constexpr int TN    = 64;           // K/V rows per iteration
static constexpr int NIT   = S_LEN / TN;   // 32
static constexpr int NTHREADS = 128;       // 4 warps
static constexpr int NQT   = S_LEN / TM;   // 32 Q tiles per head
static constexpr int NHEADS = 64;
static constexpr int TILE_BYTES = TN * 128;          // 8192 (64 rows x 128B)
static constexpr int NTILES = NHEADS * NIT;          // 2048
static constexpr uint32_t ONES2 = 0x3C003C00u;       // half2(1,1)

// scratch: pre-swizzled fp16 tiles (K, V), 16 MB each
__device__ __align__(16) uint8_t d_kh[(size_t)NTILES * TILE_BYTES];
__device__ __align__(16) uint8_t d_vh[(size_t)NTILES * TILE_BYTES];

// main-kernel dynamic SMEM layout (bytes)
static constexpr int SM_QH = 0;            // 64 x 64 fp16 SW128 (8 KB)
static constexpr int SM_QL = 8192;         // 64 x 64 fp16 SW128 (8 KB)
static constexpr int SM_ST = 16384;        // 2 stages x (K 8K | V 8K)
static constexpr int STAGE = 16384;
static constexpr int ST_V  = 8192;
static constexpr int SMEM_BYTES = SM_ST + 2 * STAGE;   // 48 KB

// ---------------------------------------------------------------------------
DINLINE uint32_t smem_u32(const void* p) {
    uint32_t a;
    asm("{ .reg .u64 t; cvta.to.shared.u64 t, %1; cvt.u32.u64 %0, t; }" : "=r"(a) : "l"(p));
    return a;
}

DINLINE float ex2f(float x) {
    float y;
    asm("ex2.approx.ftz.f32 %0, %1;" : "=f"(y) : "f"(x));
    return y;
}

// packed fp16 exp2: one MUFU op for two values
DINLINE uint32_t ex2h2(uint32_t a) {
    uint32_t y;
    asm("ex2.approx.f16x2 %0, %1;" : "=r"(y) : "r"(a));
    return y;
}

DINLINE uint32_t h2_bits(__half2 h) {
    uint32_t u;
    __builtin_memcpy(&u, &h, 4);
    return u;
}

DINLINE uint32_t sw_off(int row, int colb) {
    uint32_t off = (uint32_t)(row * 128 + colb);
    return off ^ ((off >> 3) & 0x70);
}

DINLINE uint32_t sw_addr(uint32_t base, int row, int colb) {
    return base + sw_off(row, colb);
}

DINLINE void ldmatrix_x4(uint32_t* r, uint32_t addr) {
    asm volatile("ldmatrix.sync.aligned.m8n8.x4.shared.b16 {%0,%1,%2,%3}, [%4];"
                 : "=r"(r[0]), "=r"(r[1]), "=r"(r[2]), "=r"(r[3]) : "r"(addr));
}

DINLINE void ldmatrix_x4_trans(uint32_t* r, uint32_t addr) {
    asm volatile("ldmatrix.sync.aligned.m8n8.x4.trans.shared.b16 {%0,%1,%2,%3}, [%4];"
                 : "=r"(r[0]), "=r"(r[1]), "=r"(r[2]), "=r"(r[3]) : "r"(addr));
}

DINLINE void mma_16816(float* c, const uint32_t* a, uint32_t b0, uint32_t b1) {
    asm volatile(
        "mma.sync.aligned.m16n8k16.row.col.f32.f16.f16.f32 "
        "{%0,%1,%2,%3}, {%4,%5,%6,%7}, {%8,%9}, {%0,%1,%2,%3};"
        : "+f"(c[0]), "+f"(c[1]), "+f"(c[2]), "+f"(c[3])
        : "r"(a[0]), "r"(a[1]), "r"(a[2]), "r"(a[3]), "r"(b0), "r"(b1));
}

DINLINE void sts_v2(uint32_t addr, uint32_t x, uint32_t y) {
    asm volatile("st.shared.v2.b32 [%0], {%1, %2};" :: "r"(addr), "r"(x), "r"(y) : "memory");
}

// Split-precision pack: hi = fp16(x), lo = fp16(x - hi)
DINLINE void split2(float x, float y, uint32_t& hi, uint32_t& lo) {
    __half hx = __float2half_rn(x);
    __half hy = __float2half_rn(y);
    __half lx = __float2half_rn(x - __half2float(hx));
    __half ly = __float2half_rn(y - __half2float(hy));
    hi = h2_bits(__halves2half2(hx, hy));
    lo = h2_bits(__halves2half2(lx, ly));
}

#define CP_COMMIT() asm volatile("cp.async.commit_group;" ::: "memory")
#define CP_WAIT0()  asm volatile("cp.async.wait_group 0;" ::: "memory")

// cp.async one pre-swizzled 8 KB tile (global scratch -> smem). 4 x 16B/thread.
DINLINE void cp_tile(const uint8_t* __restrict__ g, uint32_t s) {
    const int t = threadIdx.x;
#pragma unroll
    for (int i = 0; i < 4; i++) {
        int idx = t + i * NTHREADS;
        asm volatile("cp.async.cg.shared.global [%0], [%1], 16;"
                     :: "r"(s + idx * 16), "l"(g + idx * 16) : "memory");
    }
}

// ---------------------------------------------------------------------------
// Pre-pass: K/V fp32 -> pre-swizzled fp16 tiles in scratch.
// ---------------------------------------------------------------------------
__global__ void __launch_bounds__(256)
convert_kernel(const float* __restrict__ K, const float* __restrict__ V) {
    const int tile = blockIdx.x;
    const float* kg = K + (size_t)tile * (TN * HDIM);
    const float* vg = V + (size_t)tile * (TN * HDIM);
    uint8_t* okh = d_kh + (size_t)tile * TILE_BYTES;
    uint8_t* ovh = d_vh + (size_t)tile * TILE_BYTES;
    const int t = threadIdx.x;
#pragma unroll
    for (int i = 0; i < 4; i++) {
        int idx = t + i * 256;                 // float4 index, 0..1023
        int row = idx >> 4, c4 = idx & 15;
        uint32_t off = sw_off(row, c4 * 8);
        float4 kv = *reinterpret_cast<const float4*>(kg + idx * 4);
        *reinterpret_cast<uint2*>(okh + off) =
            make_uint2(h2_bits(__floats2half2_rn(kv.x, kv.y)),
                       h2_bits(__floats2half2_rn(kv.z, kv.w)));
        float4 vv = *reinterpret_cast<const float4*>(vg + idx * 4);
        *reinterpret_cast<uint2*>(ovh + off) =
            make_uint2(h2_bits(__floats2half2_rn(vv.x, vv.y)),
                       h2_bits(__floats2half2_rn(vv.z, vv.w)));
    }
}

// Q: direct gmem load -> split fp16 tiles (once per CTA, 64 rows)
DINLINE void load_q_split(const float* __restrict__ g, uint32_t shi, uint32_t slo) {
    const int t = threadIdx.x;
    const float scale = 1.4426950408889634f;   // log2(e)
#pragma unroll
    for (int i = 0; i < 8; i++) {
        int idx = t + i * NTHREADS;            // 0..1023 float4s (64 rows x 16)
        int row = idx >> 4, c4 = idx & 15;
        float4 v = *reinterpret_cast<const float4*>(g + row * HDIM + c4 * 4);
        uint32_t h0, l0, h1, l1;
        split2(v.x * scale, v.y * scale, h0, l0);
        split2(v.z * scale, v.w * scale, h1, l1);
        sts_v2(sw_addr(shi, row, c4 * 8), h0, h1);
        sts_v2(sw_addr(slo, row, c4 * 8), l0, l1);
    }
}

// ---------------------------------------------------------------------------
__global__ void __launch_bounds__(NTHREADS, 3)
attn_kernel(const float* __restrict__ Q, float* __restrict__ Out) {
    extern __shared__ char smem[];
    const uint32_t sb = smem_u32(smem);

    const int tid = threadIdx.x;
    const int w   = tid >> 5;        // 0..3
    const int lid = tid & 31;
    const int g   = lid >> 2;
    const int tig = lid & 3;

    const int bh = blockIdx.x >> 5;          // head (64)
    const int qt = blockIdx.x & 31;          // Q tile of 64 rows (32)
    const size_t head_off = (size_t)bh * S_LEN * HDIM;
    const float* qg = Q + head_off + (size_t)qt * TM * HDIM;
    float* og = Out + head_off + (size_t)qt * TM * HDIM;
    const size_t tbase = (size_t)bh * NIT;   // first K/V tile of this head

    // ---- prologue: prefetch tile 0, stage Q, build Q frags ----
    cp_tile(d_kh + tbase * TILE_BYTES, sb + SM_ST);
    cp_tile(d_vh + tbase * TILE_BYTES, sb + SM_ST + ST_V);
    CP_COMMIT();

    load_q_split(qg, sb + SM_QH, sb + SM_QL);
    __syncthreads();

    uint32_t qh[4][4], ql[4][4];
    {
        const int r   = lid & 7;
        const int sel = lid >> 3;
        const int row = 16 * w + (sel & 1) * 8 + r;
#pragma unroll
        for (int kb = 0; kb < 4; kb++) {
            int colb = kb * 32 + (sel >> 1) * 16;
            ldmatrix_x4(qh[kb], sw_addr(sb + SM_QH, row, colb));
            ldmatrix_x4(ql[kb], sw_addr(sb + SM_QL, row, colb));
        }
    }

    float oacc[8][4];
#pragma unroll
    for (int nb = 0; nb < 8; nb++)
#pragma unroll
        for (int i = 0; i < 4; i++) oacc[nb][i] = 0.f;

    float m0 = -__int_as_float(0x7f800000), m1 = m0;
    float l0 = 0.f, l1 = 0.f;

    const int lr   = lid & 7;
    const int lsel = lid >> 3;

    for (int j = 0; j < NIT; j++) {
        const uint32_t st = sb + SM_ST + (j & 1) * STAGE;

        // tile j arrived; all warps done reading the other stage (iter j-1)
        CP_WAIT0();
        __syncthreads();

        // prefetch tile j+1 into the other stage (overlaps all MMAs below)
        if (j + 1 < NIT) {
            const uint32_t stn = sb + SM_ST + ((j + 1) & 1) * STAGE;
            const size_t toff = (tbase + j + 1) * TILE_BYTES;
            cp_tile(d_kh + toff, stn);
            cp_tile(d_vh + toff, stn + ST_V);
            CP_COMMIT();
        }

        // ---- S = (Qhi + Qlo) Khi^T : 16 x 64 per warp, 64 MMAs ----
        float sacc[8][4];
#pragma unroll
        for (int nb = 0; nb < 8; nb++) {
#pragma unroll
            for (int i = 0; i < 4; i++) sacc[nb][i] = 0.f;
#pragma unroll
            for (int kbp = 0; kbp < 2; kbp++) {
                uint32_t kh[4];
                int colb = 64 * kbp + lsel * 16;
                ldmatrix_x4(kh, sw_addr(st, 8 * nb + lr, colb));
                mma_16816(sacc[nb], qh[2 * kbp],     kh[0], kh[1]);
                mma_16816(sacc[nb], qh[2 * kbp + 1], kh[2], kh[3]);
                mma_16816(sacc[nb], ql[2 * kbp],     kh[0], kh[1]);
                mma_16816(sacc[nb], ql[2 * kbp + 1], kh[2], kh[3]);
            }
        }

        // ---- online softmax: row max (fp32) ----
        float mr0 = sacc[0][0], mr1 = sacc[0][2];
#pragma unroll
        for (int nb = 0; nb < 8; nb++) {
            mr0 = fmaxf(mr0, fmaxf(sacc[nb][0], sacc[nb][1]));
            mr1 = fmaxf(mr1, fmaxf(sacc[nb][2], sacc[nb][3]));
        }
        mr0 = fmaxf(mr0, __shfl_xor_sync(0xffffffffu, mr0, 1));
        mr0 = fmaxf(mr0, __shfl_xor_sync(0xffffffffu, mr0, 2));
        mr1 = fmaxf(mr1, __shfl_xor_sync(0xffffffffu, mr1, 1));
        mr1 = fmaxf(mr1, __shfl_xor_sync(0xffffffffu, mr1, 2));

        float mn0 = fmaxf(m0, mr0), mn1 = fmaxf(m1, mr1);
        float al0 = ex2f(m0 - mn0), al1 = ex2f(m1 - mn1);
        m0 = mn0; m1 = mn1;

        // ---- P = exp2(s - mn) directly in packed fp16 (A-fragments) ----
        uint32_t pa[4][4];
#pragma unroll
        for (int kb2 = 0; kb2 < 4; kb2++) {
            pa[kb2][0] = ex2h2(h2_bits(__floats2half2_rn(sacc[2 * kb2][0] - mn0,
                                                         sacc[2 * kb2][1] - mn0)));
            pa[kb2][1] = ex2h2(h2_bits(__floats2half2_rn(sacc[2 * kb2][2] - mn1,
                                                         sacc[2 * kb2][3] - mn1)));
            pa[kb2][2] = ex2h2(h2_bits(__floats2half2_rn(sacc[2 * kb2 + 1][0] - mn0,
                                                         sacc[2 * kb2 + 1][1] - mn0)));
            pa[kb2][3] = ex2h2(h2_bits(__floats2half2_rn(sacc[2 * kb2 + 1][2] - mn1,
                                                         sacc[2 * kb2 + 1][3] - mn1)));
        }

        // ---- row sums via MMA against ones (fp32 accum of actual fp16 P) ----
        float sumacc[4] = {0.f, 0.f, 0.f, 0.f};
#pragma unroll
        for (int kb2 = 0; kb2 < 4; kb2++)
            mma_16816(sumacc, pa[kb2], ONES2, ONES2);
        l0 = l0 * al0 + sumacc[0];
        l1 = l1 * al1 + sumacc[2];

        // ---- rescale O accum ----
#pragma unroll
        for (int nb = 0; nb < 8; nb++) {
            oacc[nb][0] *= al0; oacc[nb][1] *= al0;
            oacc[nb][2] *= al1; oacc[nb][3] *= al1;
        }

        // ---- O += P V ----
#pragma unroll
        for (int nbp = 0; nbp < 4; nbp++) {
#pragma unroll
            for (int kb2 = 0; kb2 < 4; kb2++) {
                uint32_t vf[4];
                int row  = 16 * kb2 + (lsel & 1) * 8 + lr;
                int colb = 16 * (2 * nbp + (lsel >> 1));
                ldmatrix_x4_trans(vf, sw_addr(st + ST_V, row, colb));
                mma_16816(oacc[2 * nbp],     pa[kb2], vf[0], vf[1]);
                mma_16816(oacc[2 * nbp + 1], pa[kb2], vf[2], vf[3]);
            }
        }
        // no trailing sync: next iter's entry sync protects stage reuse
    }

    // ---- epilogue: O / l -> gmem ----
    float inv0 = __fdividef(1.f, l0);
    float inv1 = __fdividef(1.f, l1);
    const int row0 = 16 * w + g;
    const int row1 = row0 + 8;
#pragma unroll
    for (int nb = 0; nb < 8; nb++) {
        int col = 8 * nb + 2 * tig;
        *reinterpret_cast<float2*>(og + (size_t)row0 * HDIM + col) =
            make_float2(oacc[nb][0] * inv0, oacc[nb][1] * inv0);
        *reinterpret_cast<float2*>(og + (size_t)row1 * HDIM + col) =
            make_float2(oacc[nb][2] * inv1, oacc[nb][3] * inv1);
    }
}

// ---------------------------------------------------------------------------
extern "C" void kernel_launch(void* const* d_in, const int* in_sizes, int n_in,
                              void* d_out, int out_size) {
    const float* Q = (const float*)d_in[0];
    const float* K = (const float*)d_in[1];
    const float* V = (const float*)d_in[2];
    float* O = (float*)d_out;

    cudaFuncSetAttribute(attn_kernel, cudaFuncAttributeMaxDynamicSharedMemorySize, SMEM_BYTES);

    convert_kernel<<<NTILES, 256>>>(K, V);            // ~15 us pre-pass
    attn_kernel<<<64 * NQT, NTHREADS, SMEM_BYTES>>>(Q, O);
}